// round 7
// baseline (speedup 1.0000x reference)
#include <cuda_runtime.h>
#include <math.h>

#define NB 512
#define NT 256
#define NZ 128
#define NX 64
#define NR 1024
#define G1 296          // persistent grid: 2 blocks/SM on >=148 SMs, all co-resident
#define R2 16           // phase-2 rows per block

// ---------------- device scratch (static: no allocation allowed) ----------------
__device__ float g_h[NB * NR];
__device__ float g_z[NB * NZ];
__device__ float g_rz[NB * 2048];       // r,z gate pre-activations (gi+gh summed)
__device__ float g_in[NB * NR];         // i_n
__device__ float g_hn[NB * NR];         // h_n
__device__ float g_hid[NB * 2048];      // [hid_gate | hid_prop]
__device__ float g_loclin[NB * NZ];
__device__ float g_gp[4 * NB * NZ];     // gate-pre partials (k-split 4)
__device__ float g_pp[4 * NB * NZ];     // prop partials
__device__ float g_zall[(size_t)NT * NB * NZ];   // [T,B,Z]
__device__ unsigned g_bar;

// ---------------- helpers ----------------
__device__ __forceinline__ float sigm(float x) { return 1.0f / (1.0f + expf(-x)); }
__device__ __forceinline__ float softplus_f(float x) {
    return fmaxf(x, 0.0f) + log1pf(expf(-fabsf(x)));
}

// Software grid barrier. Release: bar.sync + leader threadfence + atomic ticket.
// Acquire: volatile (L2) spin; all cross-block data is read with __ldcg afterwards.
__device__ __forceinline__ void gbar() {
    __syncthreads();
    if (threadIdx.x == 0) {
        __threadfence();
        unsigned t = atomicAdd(&g_bar, 1u);
        unsigned tgt = (t / G1 + 1u) * G1;
        while (*((volatile unsigned*)&g_bar) < tgt) { }
    }
    __syncthreads();
}

// ---------------- tile GEMM worker: 64x32 tile, BK=16, micro 4x2, 256 threads ----
// Double-buffered: next chunk's LDGs are issued before the compute phase and
// stored to the alternate smem buffer after it -> L2 latency hidden, 1 sync/chunk.
// acc += A[bm:bm+64, :K] @ W[bn:bn+32, :K]^T   (A k-contig, W row-major [n,K])
// A is inter-block scratch -> __ldcg; W is read-only input -> plain (L1).
__device__ __forceinline__ void mm_acc(float acc[4][2],
                                       const float* __restrict__ A, int lda,
                                       const float* __restrict__ W, int ldw, int K,
                                       int bm, int bn,
                                       float (*As)[64], float (*Ws)[32])
{
    const int tid = threadIdx.x;
    const int tx = tid & 15, ty = tid >> 4;
    const int ar = tid >> 2, ac = (tid & 3) << 2;
    const float* Ap = A + (size_t)(bm + ar) * lda + ac;
    const float* Wp = W + (size_t)(bn + ar) * ldw + ac;
    const int nchunk = K >> 4;

    // prefetch chunk 0 -> buffer 0
    {
        float4 va = __ldcg((const float4*)Ap);
        As[ac + 0][ar] = va.x; As[ac + 1][ar] = va.y;
        As[ac + 2][ar] = va.z; As[ac + 3][ar] = va.w;
        if (tid < 128) {
            float4 vw = *(const float4*)Wp;
            Ws[ac + 0][ar] = vw.x; Ws[ac + 1][ar] = vw.y;
            Ws[ac + 2][ar] = vw.z; Ws[ac + 3][ar] = vw.w;
        }
    }
    __syncthreads();

    for (int c = 0; c < nchunk; c++) {
        const int buf = (c & 1) << 4;
        const int nbuf = buf ^ 16;
        float4 na, nw;
        const bool more = (c + 1 < nchunk);
        if (more) {
            na = __ldcg((const float4*)(Ap + (c + 1) * 16));
            if (tid < 128) nw = *(const float4*)(Wp + (c + 1) * 16);
        }
#pragma unroll
        for (int k = 0; k < 16; k++) {
            float4 a = *(const float4*)(&As[buf + k][ty << 2]);
            float2 w = *(const float2*)(&Ws[buf + k][tx << 1]);
            acc[0][0] += a.x * w.x; acc[0][1] += a.x * w.y;
            acc[1][0] += a.y * w.x; acc[1][1] += a.y * w.y;
            acc[2][0] += a.z * w.x; acc[2][1] += a.z * w.y;
            acc[3][0] += a.w * w.x; acc[3][1] += a.w * w.y;
        }
        if (more) {
            As[nbuf + ac + 0][ar] = na.x; As[nbuf + ac + 1][ar] = na.y;
            As[nbuf + ac + 2][ar] = na.z; As[nbuf + ac + 3][ar] = na.w;
            if (tid < 128) {
                Ws[nbuf + ac + 0][ar] = nw.x; Ws[nbuf + ac + 1][ar] = nw.y;
                Ws[nbuf + ac + 2][ar] = nw.z; Ws[nbuf + ac + 3][ar] = nw.w;
            }
        }
        __syncthreads();
    }
}

// ---------------- phase 1: the whole recurrence in ONE persistent kernel --------
__global__ void __launch_bounds__(256, 2) phase1_kernel(
    const float* __restrict__ eps,
    const float* __restrict__ w_ih, const float* __restrict__ b_ih,
    const float* __restrict__ w_hh, const float* __restrict__ b_hh,
    const float* __restrict__ tgw,  const float* __restrict__ tgb,
    const float* __restrict__ tghw, const float* __restrict__ tghb,
    const float* __restrict__ tpw,  const float* __restrict__ tpb,
    const float* __restrict__ tphw, const float* __restrict__ tphb,
    const float* __restrict__ tlw,  const float* __restrict__ tlb,
    const float* __restrict__ tsw,  const float* __restrict__ tsb)
{
    __shared__ float As[32][64];    // 2 buffers x 16 k
    __shared__ float Ws[32][32];
    __shared__ float rp[2][128];
    const int bid = blockIdx.x, tid = threadIdx.x;
    const int tx = tid & 15, ty = tid >> 4;

    for (int t = 0; t < NT; t++) {
        // ---- S1: GRU gate pre-activations [512,3072], K = 1024 (h) + 128 (z) ----
        for (int tile = bid; tile < 768; tile += G1) {
            int mt = tile / 96, nt = tile % 96;
            int bm = mt << 6, bn = nt << 5;
            if (nt < 64) {  // r,z columns: store summed gi+gh
                float acc[4][2] = {};
                mm_acc(acc, g_h, NR, w_hh, NR, NR, bm, bn, As, Ws);
                mm_acc(acc, g_z, NZ, w_ih, NZ, NZ, bm, bn, As, Ws);
#pragma unroll
                for (int i = 0; i < 4; i++) {
                    int m = bm + (ty << 2) + i;
#pragma unroll
                    for (int j = 0; j < 2; j++) {
                        int n = bn + (tx << 1) + j;
                        g_rz[m * 2048 + n] = acc[i][j] + b_ih[n] + b_hh[n];
                    }
                }
            } else {        // n columns: need i_n and h_n separately
                float acc[4][2] = {};
                mm_acc(acc, g_z, NZ, w_ih, NZ, NZ, bm, bn, As, Ws);
#pragma unroll
                for (int i = 0; i < 4; i++) {
                    int m = bm + (ty << 2) + i;
#pragma unroll
                    for (int j = 0; j < 2; j++) {
                        int n = bn + (tx << 1) + j;
                        g_in[m * 1024 + (n - 2048)] = acc[i][j] + b_ih[n];
                    }
                }
                float acc2[4][2] = {};
                mm_acc(acc2, g_h, NR, w_hh, NR, NR, bm, bn, As, Ws);
#pragma unroll
                for (int i = 0; i < 4; i++) {
                    int m = bm + (ty << 2) + i;
#pragma unroll
                    for (int j = 0; j < 2; j++) {
                        int n = bn + (tx << 1) + j;
                        g_hn[m * 1024 + (n - 2048)] = acc2[i][j] + b_hh[n];
                    }
                }
            }
        }
        gbar();
        // ---- S2: GRU nonlinearity -> h_new ----
        for (int idx = bid * 256 + tid; idx < NB * NR; idx += G1 * 256) {
            int b = idx >> 10, j = idx & 1023;
            float r  = sigm(__ldcg(&g_rz[b * 2048 + j]));
            float zz = sigm(__ldcg(&g_rz[b * 2048 + 1024 + j]));
            float nn = tanhf(__ldcg(&g_in[idx]) + r * __ldcg(&g_hn[idx]));
            float hp = __ldcg(&g_h[idx]);
            g_h[idx] = (1.0f - zz) * nn + zz * hp;
        }
        gbar();
        // ---- S3: hid = relu(h @ [tgw;tpw]^T + b)  [512,2048]  +  loclin [512,128] ----
        for (int tile = bid; tile < 544; tile += G1) {
            if (tile < 512) {
                int mt = tile >> 6, nt = tile & 63;
                int bm = mt << 6, bn = nt << 5;
                const float* W; const float* bb; int nl;
                if (bn < 1024) { W = tgw; bb = tgb; nl = bn; }
                else           { W = tpw; bb = tpb; nl = bn - 1024; }
                float acc[4][2] = {};
                mm_acc(acc, g_h, NR, W, NR, NR, bm, nl, As, Ws);
#pragma unroll
                for (int i = 0; i < 4; i++) {
                    int m = bm + (ty << 2) + i;
#pragma unroll
                    for (int j = 0; j < 2; j++) {
                        int c = (tx << 1) + j;
                        g_hid[m * 2048 + bn + c] = fmaxf(acc[i][j] + bb[nl + c], 0.0f);
                    }
                }
            } else {
                int t2 = tile - 512;
                int bm = (t2 >> 2) << 6, bn = (t2 & 3) << 5;
                float acc[4][2] = {};
                mm_acc(acc, g_h, NR, tlw, NR, NR, bm, bn, As, Ws);
#pragma unroll
                for (int i = 0; i < 4; i++) {
                    int m = bm + (ty << 2) + i;
#pragma unroll
                    for (int j = 0; j < 2; j++) {
                        int n = bn + (tx << 1) + j;
                        g_loclin[m * 128 + n] = acc[i][j] + tlb[n];
                    }
                }
            }
        }
        gbar();
        // ---- S4: gatep/prop [512,128] K=1024, k-split by 4 for balance ----
        for (int tile = bid; tile < 256; tile += G1) {
            int g = tile >> 7;
            int rem = tile & 127;
            int bm = (rem >> 4) << 6;
            int bn = ((rem >> 2) & 3) << 5;
            int ks = rem & 3;
            const float* A = g_hid + (g ? 1024 : 0) + ks * 256;
            const float* W = (g ? tphw : tghw) + ks * 256;
            float acc[4][2] = {};
            mm_acc(acc, A, 2048, W, NR, 256, bm, bn, As, Ws);
            float* dst = (g ? g_pp : g_gp) + ks * (NB * NZ);
#pragma unroll
            for (int i = 0; i < 4; i++) {
                int m = bm + (ty << 2) + i;
#pragma unroll
                for (int j = 0; j < 2; j++) {
                    int n = bn + (tx << 1) + j;
                    dst[m * 128 + n] = acc[i][j];
                }
            }
        }
        gbar();
        // ---- S5: finalize z_t (reduce partials + fused scale GEMM + reparam) ----
        if (bid < 256) {
            int row = tid >> 7;              // 0/1
            int b = (bid << 1) + row;
            int i = tid & 127;
            float gp = tghb[i], pp = tphb[i];
#pragma unroll
            for (int ks = 0; ks < 4; ks++) {
                gp += __ldcg(&g_gp[ks * (NB * NZ) + b * 128 + i]);
                pp += __ldcg(&g_pp[ks * (NB * NZ) + b * 128 + i]);
            }
            rp[row][i] = fmaxf(pp, 0.0f);
            __syncthreads();
            float s = tsb[i];
            const float* wr = tsw + (size_t)i * 128;
            const float* rpr = rp[row];
#pragma unroll 8
            for (int j = 0; j < 128; j += 4) {
                float4 w = *(const float4*)(wr + j);
                s += rpr[j] * w.x + rpr[j + 1] * w.y + rpr[j + 2] * w.z + rpr[j + 3] * w.w;
            }
            float gate = sigm(gp);
            float loc = (1.0f - gate) * __ldcg(&g_loclin[b * 128 + i]) + gate * pp;
            float zv = loc + softplus_f(s) * eps[((size_t)b * NT + t) * NZ + i];
            g_z[b * 128 + i] = zv;
            g_zall[((size_t)t * NB + b) * NZ + i] = zv;
        }
        gbar();
    }
}

// ---------------- phase 2: obs transformer, fully fused per-row ----------------
__device__ __forceinline__ void obs_path(float acc[4],
                                         const float* __restrict__ wih,
                                         const float* __restrict__ bih,
                                         const float* __restrict__ whz,
                                         float (*zs)[128], float (*hs)[512], int tid)
{
    const int i = tid & 63, rg = tid >> 6;
    for (int half = 0; half < 2; half++) {
        int u0 = half * 512 + tid * 2;
        const float* w0 = wih + (size_t)u0 * 128;
        const float* w1 = w0 + 128;
        float b0 = bih[u0], b1 = bih[u0 + 1];
        for (int rc = 0; rc < 2; rc++) {
            float a0[8], a1[8];
#pragma unroll
            for (int r = 0; r < 8; r++) { a0[r] = b0; a1[r] = b1; }
            for (int k = 0; k < 128; k += 4) {
                float4 wv0 = *(const float4*)(w0 + k);
                float4 wv1 = *(const float4*)(w1 + k);
#pragma unroll
                for (int r = 0; r < 8; r++) {
                    float4 zv = *(const float4*)&zs[rc * 8 + r][k];
                    a0[r] += zv.x * wv0.x + zv.y * wv0.y + zv.z * wv0.z + zv.w * wv0.w;
                    a1[r] += zv.x * wv1.x + zv.y * wv1.y + zv.z * wv1.z + zv.w * wv1.w;
                }
            }
            int uu = tid * 2;
#pragma unroll
            for (int r = 0; r < 8; r++) {
                hs[rc * 8 + r][uu]     = fmaxf(a0[r], 0.0f);
                hs[rc * 8 + r][uu + 1] = fmaxf(a1[r], 0.0f);
            }
        }
        __syncthreads();
        const float* wr = whz + (size_t)i * 1024 + half * 512;
        for (int k = 0; k < 512; k += 4) {
            float4 wv = *(const float4*)(wr + k);
#pragma unroll
            for (int r4 = 0; r4 < 4; r4++) {
                const float* h = &hs[rg * 4 + r4][k];
                acc[r4] += h[0] * wv.x + h[1] * wv.y + h[2] * wv.z + h[3] * wv.w;
            }
        }
        __syncthreads();
    }
}

__global__ void __launch_bounds__(256) phase2_kernel(
    const float* __restrict__ ogw, const float* __restrict__ ogb,
    const float* __restrict__ oghw, const float* __restrict__ oghb,
    const float* __restrict__ opw, const float* __restrict__ opb,
    const float* __restrict__ ophw, const float* __restrict__ ophb,
    const float* __restrict__ olw, const float* __restrict__ olb,
    const float* __restrict__ osw, const float* __restrict__ osb,
    float* __restrict__ out)
{
    __shared__ float zs[R2][128];
    __shared__ float hs[R2][512];
    const int tid = threadIdx.x;
    const size_t base = (size_t)blockIdx.x * R2;   // global row = t*512 + b

    for (int idx = tid; idx < R2 * 128 / 4; idx += 256) {
        int r = idx >> 5, c = (idx & 31) << 2;
        *(float4*)&zs[r][c] = *(const float4*)&g_zall[(base + r) * 128 + c];
    }
    __syncthreads();

    const int i = tid & 63, rg = tid >> 6;
    float accg[4] = {0.f, 0.f, 0.f, 0.f};
    float accp[4] = {0.f, 0.f, 0.f, 0.f};
    obs_path(accg, ogw, ogb, oghw, zs, hs, tid);
    obs_path(accp, opw, opb, ophw, zs, hs, tid);

    float gate[4], prop[4];
    float (*ps)[64] = (float(*)[64])hs;   // reuse hs as relu(prop) [16][64]
#pragma unroll
    for (int r4 = 0; r4 < 4; r4++) {
        gate[r4] = sigm(accg[r4] + oghb[i]);
        prop[r4] = accp[r4] + ophb[i];
        ps[rg * 4 + r4][i] = fmaxf(prop[r4], 0.0f);
    }
    __syncthreads();

    float s[4], loc[4];
#pragma unroll
    for (int r4 = 0; r4 < 4; r4++) { s[r4] = osb[i]; loc[r4] = olb[i]; }
    const float* wsr = osw + (size_t)i * 64;
    for (int j = 0; j < 64; j += 4) {
        float4 wv = *(const float4*)(wsr + j);
#pragma unroll
        for (int r4 = 0; r4 < 4; r4++) {
            const float* p = &ps[rg * 4 + r4][j];
            s[r4] += p[0] * wv.x + p[1] * wv.y + p[2] * wv.z + p[3] * wv.w;
        }
    }
    const float* wlr = olw + (size_t)i * 128;
    for (int k = 0; k < 128; k += 4) {
        float4 wv = *(const float4*)(wlr + k);
#pragma unroll
        for (int r4 = 0; r4 < 4; r4++) {
            float4 zv = *(const float4*)&zs[rg * 4 + r4][k];
            loc[r4] += zv.x * wv.x + zv.y * wv.y + zv.z * wv.z + zv.w * wv.w;
        }
    }
#pragma unroll
    for (int r4 = 0; r4 < 4; r4++) {
        size_t gr = base + rg * 4 + r4;
        int tt = (int)(gr >> 9);
        int bb = (int)(gr & 511);
        float lo = (1.0f - gate[r4]) * loc[r4] + gate[r4] * prop[r4];
        float sc = softplus_f(s[r4]);
        out[((size_t)bb * NT + tt) * 128 + i]      = lo;
        out[((size_t)bb * NT + tt) * 128 + 64 + i] = sc;
    }
}

// ---------------- prep: init state + reset barrier ----------------
__global__ void prep_kernel(const float* __restrict__ z0, const float* __restrict__ h0)
{
    int idx = blockIdx.x * blockDim.x + threadIdx.x;
    if (idx == 0) g_bar = 0u;
    if (idx < NB * NR) g_h[idx] = h0[idx & (NR - 1)];
    if (idx < NB * NZ) g_z[idx] = z0[idx & (NZ - 1)];
}

// ---------------- host launcher: 3 graph nodes total ----------------
extern "C" void kernel_launch(void* const* d_in, const int* in_sizes, int n_in,
                              void* d_out, int out_size)
{
    (void)in_sizes; (void)n_in; (void)out_size;
    const float* eps      = (const float*)d_in[1];
    const float* z0       = (const float*)d_in[2];
    const float* h0       = (const float*)d_in[3];
    const float* gru_w_ih = (const float*)d_in[4];
    const float* gru_b_ih = (const float*)d_in[5];
    const float* gru_w_hh = (const float*)d_in[6];
    const float* gru_b_hh = (const float*)d_in[7];
    const float* tg_ih_w  = (const float*)d_in[8];
    const float* tg_ih_b  = (const float*)d_in[9];
    const float* tg_hz_w  = (const float*)d_in[10];
    const float* tg_hz_b  = (const float*)d_in[11];
    const float* tp_ih_w  = (const float*)d_in[12];
    const float* tp_ih_b  = (const float*)d_in[13];
    const float* tp_hz_w  = (const float*)d_in[14];
    const float* tp_hz_b  = (const float*)d_in[15];
    const float* tl_w     = (const float*)d_in[16];
    const float* tl_b     = (const float*)d_in[17];
    const float* ts_w     = (const float*)d_in[18];
    const float* ts_b     = (const float*)d_in[19];
    const float* og_ih_w  = (const float*)d_in[20];
    const float* og_ih_b  = (const float*)d_in[21];
    const float* og_hz_w  = (const float*)d_in[22];
    const float* og_hz_b  = (const float*)d_in[23];
    const float* op_ih_w  = (const float*)d_in[24];
    const float* op_ih_b  = (const float*)d_in[25];
    const float* op_hz_w  = (const float*)d_in[26];
    const float* op_hz_b  = (const float*)d_in[27];
    const float* ol_w     = (const float*)d_in[28];
    const float* ol_b     = (const float*)d_in[29];
    const float* os_w     = (const float*)d_in[30];
    const float* os_b     = (const float*)d_in[31];
    float* out = (float*)d_out;

    prep_kernel<<<(NB * NR + 255) / 256, 256>>>(z0, h0);
    phase1_kernel<<<G1, 256>>>(eps,
        gru_w_ih, gru_b_ih, gru_w_hh, gru_b_hh,
        tg_ih_w, tg_ih_b, tg_hz_w, tg_hz_b,
        tp_ih_w, tp_ih_b, tp_hz_w, tp_hz_b,
        tl_w, tl_b, ts_w, ts_b);
    phase2_kernel<<<(NT * NB) / R2, 256>>>(
        og_ih_w, og_ih_b, og_hz_w, og_hz_b,
        op_ih_w, op_ih_b, op_hz_w, op_hz_b,
        ol_w, ol_b, os_w, os_b, out);
}

// round 8
// speedup vs baseline: 2.4184x; 2.4184x over previous
#include <cuda_runtime.h>
#include <math.h>

#define NB 512
#define NT 256
#define NZ 128
#define NX 64
#define NR 1024
#define G1 148          // persistent grid: 1 block/SM, all co-resident
#define NTH 512
#define R2 16           // phase-2 rows per block
#define LSTR 68         // smem row stride (floats): conflict-free frag loads

// ---------------- device scratch (static: no allocation allowed) ----------------
__device__ __align__(16) float    g_h[NB * NR];        // fp32 recurrence carry
__device__ __align__(16) unsigned g_htf[NB * NR];      // tf32 bits of h (GEMM A)
__device__ __align__(16) unsigned g_ztf[NB * NZ];      // tf32 bits of z_prev
__device__ __align__(16) float    g_rz[NB * 2048];
__device__ __align__(16) float    g_in[NB * NR];
__device__ __align__(16) float    g_hn[NB * NR];
__device__ __align__(16) unsigned g_hidtf[NB * 2048];  // tf32 bits of relu(hid)
__device__ __align__(16) float    g_loclin[NB * NZ];
__device__ __align__(16) float    g_gp[4 * NB * NZ];
__device__ __align__(16) float    g_pp[4 * NB * NZ];
__device__ __align__(16) float    g_zall[(size_t)NT * NB * NZ];  // [T,B,Z] fp32
// tf32-rounded weight copies (converted once per launch)
__device__ __align__(16) unsigned g_wih[3072 * NZ];
__device__ __align__(16) unsigned g_whh[3072 * NR];
__device__ __align__(16) unsigned g_tgwc[1024 * NR];
__device__ __align__(16) unsigned g_tpwc[1024 * NR];
__device__ __align__(16) unsigned g_tghwc[NZ * NR];
__device__ __align__(16) unsigned g_tphwc[NZ * NR];
__device__ __align__(16) unsigned g_tlwc[NZ * NR];
__device__ unsigned g_bar;   // zero-init; monotonic tickets, never reset

// ---------------- helpers ----------------
__device__ __forceinline__ float sigm(float x) { return 1.0f / (1.0f + expf(-x)); }
__device__ __forceinline__ float softplus_f(float x) {
    return fmaxf(x, 0.0f) + log1pf(expf(-fabsf(x)));
}
__device__ __forceinline__ unsigned f2tf(float x) {
    unsigned r; asm("cvt.rna.tf32.f32 %0, %1;" : "=r"(r) : "f"(x)); return r;
}
__device__ __forceinline__ void mma_tf32(float c[4],
    unsigned a0, unsigned a1, unsigned a2, unsigned a3, unsigned b0, unsigned b1)
{
    asm volatile(
        "mma.sync.aligned.m16n8k8.row.col.f32.tf32.tf32.f32 "
        "{%0,%1,%2,%3},{%4,%5,%6,%7},{%8,%9},{%0,%1,%2,%3};"
        : "+f"(c[0]), "+f"(c[1]), "+f"(c[2]), "+f"(c[3])
        : "r"(a0), "r"(a1), "r"(a2), "r"(a3), "r"(b0), "r"(b1));
}

// Software grid barrier (monotonic tickets — works across replays without reset)
__device__ __forceinline__ void gbar() {
    __syncthreads();
    if (threadIdx.x == 0) {
        __threadfence();
        unsigned t = atomicAdd(&g_bar, 1u);
        unsigned tgt = (t / G1 + 1u) * G1;
        while (*((volatile unsigned*)&g_bar) < tgt) { }
    }
    __syncthreads();
}

// ---- TC tile worker: block tile 64x64, 16 warps of 16x16, BK=64 ----
// c[nf][0..3]: m16n8k8 C frag; A rows bm.., W rows bn.. (both K-contig, tf32 bits)
// A = per-step activations -> __ldcg (L2, coherent); W = static tf32 weights -> __ldg
__device__ __forceinline__ void mm_tc(float c[2][4],
    const unsigned* __restrict__ A, int lda,
    const unsigned* __restrict__ W, int ldw, int K,
    int bm, int bn, unsigned* As, unsigned* Ws)
{
    const int tid = threadIdx.x;
    const int lane = tid & 31, wid = tid >> 5;
    const int m_off = (wid & 3) << 4, n_off = (wid >> 2) << 4;
    const int gq = lane >> 2, l4 = lane & 3;
    const int sr = tid >> 3, sc = (tid & 7) << 3;
    const uint4* Ap = (const uint4*)(A + (size_t)(bm + sr) * lda + sc);
    const uint4* Wp = (const uint4*)(W + (size_t)(bn + sr) * ldw + sc);
    const int nch = K >> 6;
    uint4 ra0 = __ldcg(Ap), ra1 = __ldcg(Ap + 1);
    uint4 rw0 = __ldg(Wp), rw1 = __ldg(Wp + 1);
    for (int ch = 0; ch < nch; ch++) {
        *(uint4*)&As[sr * LSTR + sc]     = ra0;
        *(uint4*)&As[sr * LSTR + sc + 4] = ra1;
        *(uint4*)&Ws[sr * LSTR + sc]     = rw0;
        *(uint4*)&Ws[sr * LSTR + sc + 4] = rw1;
        __syncthreads();
        if (ch + 1 < nch) {
            ra0 = __ldcg(Ap + (ch + 1) * 16); ra1 = __ldcg(Ap + (ch + 1) * 16 + 1);
            rw0 = __ldg(Wp + (ch + 1) * 16);  rw1 = __ldg(Wp + (ch + 1) * 16 + 1);
        }
        const unsigned* Am0 = &As[(m_off + gq) * LSTR + l4];
        const unsigned* Am1 = Am0 + 8 * LSTR;
        const unsigned* Bn0 = &Ws[(n_off + gq) * LSTR + l4];
        const unsigned* Bn1 = Bn0 + 8 * LSTR;
#pragma unroll
        for (int ks = 0; ks < 8; ks++) {
            const int k0 = ks << 3;
            unsigned a0 = Am0[k0], a2 = Am0[k0 + 4];
            unsigned a1 = Am1[k0], a3 = Am1[k0 + 4];
            unsigned b0 = Bn0[k0], b1 = Bn0[k0 + 4];
            unsigned b2 = Bn1[k0], b3 = Bn1[k0 + 4];
            mma_tf32(c[0], a0, a1, a2, a3, b0, b1);
            mma_tf32(c[1], a0, a1, a2, a3, b2, b3);
        }
        __syncthreads();
    }
}

// ---------------- phase 1: whole recurrence in ONE persistent kernel --------
__global__ void __launch_bounds__(NTH, 1) phase1_kernel(
    const float* __restrict__ eps,
    const float* __restrict__ z0,   const float* __restrict__ h0,
    const float* __restrict__ w_ih, const float* __restrict__ b_ih,
    const float* __restrict__ w_hh, const float* __restrict__ b_hh,
    const float* __restrict__ tgw,  const float* __restrict__ tgb,
    const float* __restrict__ tghw, const float* __restrict__ tghb,
    const float* __restrict__ tpw,  const float* __restrict__ tpb,
    const float* __restrict__ tphw, const float* __restrict__ tphb,
    const float* __restrict__ tlw,  const float* __restrict__ tlb,
    const float* __restrict__ tsw,  const float* __restrict__ tsb)
{
    __shared__ __align__(16) unsigned As[64 * LSTR];
    __shared__ __align__(16) unsigned Ws[64 * LSTR];
    __shared__ float rp[4][128];
    const int bid = blockIdx.x, tid = threadIdx.x;
    const int lane = tid & 31, wid = tid >> 5;
    const int m_off = (wid & 3) << 4, n_off = (wid >> 2) << 4;
    const int gq = lane >> 2, l4 = lane & 3;
    const int gidx = bid * NTH + tid, gstride = G1 * NTH;

    // ---- per-launch init: tf32 weight copies + state ----
    for (int i = gidx; i < 3072 * NZ; i += gstride) g_wih[i]  = f2tf(w_ih[i]);
    for (int i = gidx; i < 3072 * NR; i += gstride) g_whh[i]  = f2tf(w_hh[i]);
    for (int i = gidx; i < 1024 * NR; i += gstride) g_tgwc[i] = f2tf(tgw[i]);
    for (int i = gidx; i < 1024 * NR; i += gstride) g_tpwc[i] = f2tf(tpw[i]);
    for (int i = gidx; i < NZ * NR;  i += gstride) g_tghwc[i] = f2tf(tghw[i]);
    for (int i = gidx; i < NZ * NR;  i += gstride) g_tphwc[i] = f2tf(tphw[i]);
    for (int i = gidx; i < NZ * NR;  i += gstride) g_tlwc[i]  = f2tf(tlw[i]);
    for (int i = gidx; i < NB * NR;  i += gstride) {
        float v = h0[i & (NR - 1)];
        g_h[i] = v; g_htf[i] = f2tf(v);
    }
    for (int i = gidx; i < NB * NZ;  i += gstride) g_ztf[i] = f2tf(z0[i & (NZ - 1)]);
    gbar();

    for (int t = 0; t < NT; t++) {
        // ---- S1: GRU gate pre-activations [512,3072], K = 1024(h) + 128(z) ----
        for (int tile = bid; tile < 384; tile += G1) {
            int nt = tile >> 3, mt = tile & 7;
            int bm = mt << 6, bn = nt << 6;
            int er0 = bm + m_off + gq, er1 = er0 + 8;
            float c[2][4] = {};
            if (nt < 32) {      // r,z columns: gi+gh summed
                mm_tc(c, g_htf, NR, g_whh, NR, NR, bm, bn, As, Ws);
                mm_tc(c, g_ztf, NZ, g_wih, NZ, NZ, bm, bn, As, Ws);
#pragma unroll
                for (int nf = 0; nf < 2; nf++) {
                    int col = bn + n_off + (nf << 3) + (l4 << 1);
                    float bs0 = b_ih[col] + b_hh[col];
                    float bs1 = b_ih[col + 1] + b_hh[col + 1];
                    *(float2*)&g_rz[er0 * 2048 + col] = make_float2(c[nf][0] + bs0, c[nf][1] + bs1);
                    *(float2*)&g_rz[er1 * 2048 + col] = make_float2(c[nf][2] + bs0, c[nf][3] + bs1);
                }
            } else {            // n columns: i_n and h_n separately
                mm_tc(c, g_ztf, NZ, g_wih, NZ, NZ, bm, bn, As, Ws);
#pragma unroll
                for (int nf = 0; nf < 2; nf++) {
                    int col = bn + n_off + (nf << 3) + (l4 << 1);
                    int nn = col - 2048;
                    *(float2*)&g_in[er0 * 1024 + nn] = make_float2(c[nf][0] + b_ih[col], c[nf][1] + b_ih[col + 1]);
                    *(float2*)&g_in[er1 * 1024 + nn] = make_float2(c[nf][2] + b_ih[col], c[nf][3] + b_ih[col + 1]);
                    c[nf][0] = c[nf][1] = c[nf][2] = c[nf][3] = 0.0f;
                }
                mm_tc(c, g_htf, NR, g_whh, NR, NR, bm, bn, As, Ws);
#pragma unroll
                for (int nf = 0; nf < 2; nf++) {
                    int col = bn + n_off + (nf << 3) + (l4 << 1);
                    int nn = col - 2048;
                    *(float2*)&g_hn[er0 * 1024 + nn] = make_float2(c[nf][0] + b_hh[col], c[nf][1] + b_hh[col + 1]);
                    *(float2*)&g_hn[er1 * 1024 + nn] = make_float2(c[nf][2] + b_hh[col], c[nf][3] + b_hh[col + 1]);
                }
            }
        }
        gbar();
        // ---- S2: GRU nonlinearity -> h_new (fp32 carry + tf32 copy) ----
        for (int idx = gidx; idx < NB * NR; idx += gstride) {
            int b = idx >> 10, j = idx & 1023;
            float r  = sigm(__ldcg(&g_rz[b * 2048 + j]));
            float zz = sigm(__ldcg(&g_rz[b * 2048 + 1024 + j]));
            float nn = tanhf(__ldcg(&g_in[idx]) + r * __ldcg(&g_hn[idx]));
            float hv = (1.0f - zz) * nn + zz * g_h[idx];
            g_h[idx] = hv;
            g_htf[idx] = f2tf(hv);
        }
        gbar();
        // ---- S3: hid = relu(h@[tgw;tpw]^T+b) [512,2048] + loclin [512,128] ----
        for (int tile = bid; tile < 272; tile += G1) {
            int er0, er1;
            if (tile < 256) {
                int nt = tile >> 3, mt = tile & 7;
                int bm = mt << 6, bn = nt << 6;
                er0 = bm + m_off + gq; er1 = er0 + 8;
                const unsigned* Wm; const float* bb; int nl;
                if (bn < 1024) { Wm = g_tgwc; bb = tgb; nl = bn; }
                else           { Wm = g_tpwc; bb = tpb; nl = bn - 1024; }
                float c[2][4] = {};
                mm_tc(c, g_htf, NR, Wm, NR, NR, bm, nl, As, Ws);
#pragma unroll
                for (int nf = 0; nf < 2; nf++) {
                    int lc = n_off + (nf << 3) + (l4 << 1);
                    int colh = bn + lc, colw = nl + lc;
                    float b0 = bb[colw], b1 = bb[colw + 1];
                    uint2 u0 = make_uint2(f2tf(fmaxf(c[nf][0] + b0, 0.0f)),
                                          f2tf(fmaxf(c[nf][1] + b1, 0.0f)));
                    uint2 u1 = make_uint2(f2tf(fmaxf(c[nf][2] + b0, 0.0f)),
                                          f2tf(fmaxf(c[nf][3] + b1, 0.0f)));
                    *(uint2*)&g_hidtf[er0 * 2048 + colh] = u0;
                    *(uint2*)&g_hidtf[er1 * 2048 + colh] = u1;
                }
            } else {
                int t2 = tile - 256;                  // 0..15: loclin 8m x 2n
                int bm = (t2 >> 1) << 6, bn = (t2 & 1) << 6;
                er0 = bm + m_off + gq; er1 = er0 + 8;
                float c[2][4] = {};
                mm_tc(c, g_htf, NR, g_tlwc, NR, NR, bm, bn, As, Ws);
#pragma unroll
                for (int nf = 0; nf < 2; nf++) {
                    int col = bn + n_off + (nf << 3) + (l4 << 1);
                    *(float2*)&g_loclin[er0 * 128 + col] = make_float2(c[nf][0] + tlb[col], c[nf][1] + tlb[col + 1]);
                    *(float2*)&g_loclin[er1 * 128 + col] = make_float2(c[nf][2] + tlb[col], c[nf][3] + tlb[col + 1]);
                }
            }
        }
        gbar();
        // ---- S4: gatep/prop [512,128] K=1024 k-split4 (128 tiles, 1 wave) ----
        for (int tile = bid; tile < 128; tile += G1) {
            int gg = tile >> 6;
            int rem = tile & 63;
            int ks = rem & 3, nt = (rem >> 2) & 1, mt = rem >> 3;
            int bm = mt << 6, bn = nt << 6;
            const unsigned* Aq = g_hidtf + (gg ? 1024 : 0) + (ks << 8);
            const unsigned* Wq = (gg ? g_tphwc : g_tghwc) + (ks << 8);
            float c[2][4] = {};
            mm_tc(c, Aq, 2048, Wq, NR, 256, bm, bn, As, Ws);
            float* dst = (gg ? g_pp : g_gp) + ks * (NB * NZ);
            int er0 = bm + m_off + gq, er1 = er0 + 8;
#pragma unroll
            for (int nf = 0; nf < 2; nf++) {
                int col = bn + n_off + (nf << 3) + (l4 << 1);
                *(float2*)&dst[er0 * 128 + col] = make_float2(c[nf][0], c[nf][1]);
                *(float2*)&dst[er1 * 128 + col] = make_float2(c[nf][2], c[nf][3]);
            }
        }
        gbar();
        // ---- S5: finalize z_t (reduce + fused scale GEMM + reparam), fp32 ----
        if (bid < 128) {
            int row = tid >> 7;            // 0..3
            int b = (bid << 2) + row;
            int i = tid & 127;
            float gp = tghb[i], pp = tphb[i];
#pragma unroll
            for (int ks = 0; ks < 4; ks++) {
                gp += __ldcg(&g_gp[ks * (NB * NZ) + b * 128 + i]);
                pp += __ldcg(&g_pp[ks * (NB * NZ) + b * 128 + i]);
            }
            rp[row][i] = fmaxf(pp, 0.0f);
            __syncthreads();
            float s = tsb[i];
            const float* wr = tsw + (size_t)i * 128;
            const float* rpr = rp[row];
#pragma unroll 8
            for (int j = 0; j < 128; j += 4) {
                float4 w = *(const float4*)(wr + j);
                s += rpr[j] * w.x + rpr[j + 1] * w.y + rpr[j + 2] * w.z + rpr[j + 3] * w.w;
            }
            float gate = sigm(gp);
            float loc = (1.0f - gate) * __ldcg(&g_loclin[b * 128 + i]) + gate * pp;
            float zv = loc + softplus_f(s) * eps[((size_t)b * NT + t) * NZ + i];
            g_ztf[b * 128 + i] = f2tf(zv);
            g_zall[((size_t)t * NB + b) * NZ + i] = zv;
        }
        gbar();
    }
}

// ---------------- phase 2: obs transformer, fully fused per-row (fp32) --------
__device__ __forceinline__ void obs_path(float acc[4],
                                         const float* __restrict__ wih,
                                         const float* __restrict__ bih,
                                         const float* __restrict__ whz,
                                         float (*zs)[128], float (*hs)[512], int tid)
{
    const int i = tid & 63, rg = tid >> 6;
    for (int half = 0; half < 2; half++) {
        int u0 = half * 512 + tid * 2;
        const float* w0 = wih + (size_t)u0 * 128;
        const float* w1 = w0 + 128;
        float b0 = bih[u0], b1 = bih[u0 + 1];
        for (int rc = 0; rc < 2; rc++) {
            float a0[8], a1[8];
#pragma unroll
            for (int r = 0; r < 8; r++) { a0[r] = b0; a1[r] = b1; }
            for (int k = 0; k < 128; k += 4) {
                float4 wv0 = *(const float4*)(w0 + k);
                float4 wv1 = *(const float4*)(w1 + k);
#pragma unroll
                for (int r = 0; r < 8; r++) {
                    float4 zv = *(const float4*)&zs[rc * 8 + r][k];
                    a0[r] += zv.x * wv0.x + zv.y * wv0.y + zv.z * wv0.z + zv.w * wv0.w;
                    a1[r] += zv.x * wv1.x + zv.y * wv1.y + zv.z * wv1.z + zv.w * wv1.w;
                }
            }
            int uu = tid * 2;
#pragma unroll
            for (int r = 0; r < 8; r++) {
                hs[rc * 8 + r][uu]     = fmaxf(a0[r], 0.0f);
                hs[rc * 8 + r][uu + 1] = fmaxf(a1[r], 0.0f);
            }
        }
        __syncthreads();
        const float* wr = whz + (size_t)i * 1024 + half * 512;
        for (int k = 0; k < 512; k += 4) {
            float4 wv = *(const float4*)(wr + k);
#pragma unroll
            for (int r4 = 0; r4 < 4; r4++) {
                const float* h = &hs[rg * 4 + r4][k];
                acc[r4] += h[0] * wv.x + h[1] * wv.y + h[2] * wv.z + h[3] * wv.w;
            }
        }
        __syncthreads();
    }
}

__global__ void __launch_bounds__(256) phase2_kernel(
    const float* __restrict__ ogw, const float* __restrict__ ogb,
    const float* __restrict__ oghw, const float* __restrict__ oghb,
    const float* __restrict__ opw, const float* __restrict__ opb,
    const float* __restrict__ ophw, const float* __restrict__ ophb,
    const float* __restrict__ olw, const float* __restrict__ olb,
    const float* __restrict__ osw, const float* __restrict__ osb,
    float* __restrict__ out)
{
    __shared__ float zs[R2][128];
    __shared__ float hs[R2][512];
    const int tid = threadIdx.x;
    const size_t base = (size_t)blockIdx.x * R2;

    for (int idx = tid; idx < R2 * 128 / 4; idx += 256) {
        int r = idx >> 5, c = (idx & 31) << 2;
        *(float4*)&zs[r][c] = *(const float4*)&g_zall[(base + r) * 128 + c];
    }
    __syncthreads();

    const int i = tid & 63, rg = tid >> 6;
    float accg[4] = {0.f, 0.f, 0.f, 0.f};
    float accp[4] = {0.f, 0.f, 0.f, 0.f};
    obs_path(accg, ogw, ogb, oghw, zs, hs, tid);
    obs_path(accp, opw, opb, ophw, zs, hs, tid);

    float gate[4], prop[4];
    float (*ps)[64] = (float(*)[64])hs;
#pragma unroll
    for (int r4 = 0; r4 < 4; r4++) {
        gate[r4] = sigm(accg[r4] + oghb[i]);
        prop[r4] = accp[r4] + ophb[i];
        ps[rg * 4 + r4][i] = fmaxf(prop[r4], 0.0f);
    }
    __syncthreads();

    float s[4], loc[4];
#pragma unroll
    for (int r4 = 0; r4 < 4; r4++) { s[r4] = osb[i]; loc[r4] = olb[i]; }
    const float* wsr = osw + (size_t)i * 64;
    for (int j = 0; j < 64; j += 4) {
        float4 wv = *(const float4*)(wsr + j);
#pragma unroll
        for (int r4 = 0; r4 < 4; r4++) {
            const float* p = &ps[rg * 4 + r4][j];
            s[r4] += p[0] * wv.x + p[1] * wv.y + p[2] * wv.z + p[3] * wv.w;
        }
    }
    const float* wlr = olw + (size_t)i * 128;
    for (int k = 0; k < 128; k += 4) {
        float4 wv = *(const float4*)(wlr + k);
#pragma unroll
        for (int r4 = 0; r4 < 4; r4++) {
            float4 zv = *(const float4*)&zs[rg * 4 + r4][k];
            loc[r4] += zv.x * wv.x + zv.y * wv.y + zv.z * wv.z + zv.w * wv.w;
        }
    }
#pragma unroll
    for (int r4 = 0; r4 < 4; r4++) {
        size_t gr = base + rg * 4 + r4;
        int tt = (int)(gr >> 9);
        int bb = (int)(gr & 511);
        float lo = (1.0f - gate[r4]) * loc[r4] + gate[r4] * prop[r4];
        float sc = softplus_f(s[r4]);
        out[((size_t)bb * NT + tt) * 128 + i]      = lo;
        out[((size_t)bb * NT + tt) * 128 + 64 + i] = sc;
    }
}

// ---------------- host launcher: 2 graph nodes ----------------
extern "C" void kernel_launch(void* const* d_in, const int* in_sizes, int n_in,
                              void* d_out, int out_size)
{
    (void)in_sizes; (void)n_in; (void)out_size;
    const float* eps      = (const float*)d_in[1];
    const float* z0       = (const float*)d_in[2];
    const float* h0       = (const float*)d_in[3];
    const float* gru_w_ih = (const float*)d_in[4];
    const float* gru_b_ih = (const float*)d_in[5];
    const float* gru_w_hh = (const float*)d_in[6];
    const float* gru_b_hh = (const float*)d_in[7];
    const float* tg_ih_w  = (const float*)d_in[8];
    const float* tg_ih_b  = (const float*)d_in[9];
    const float* tg_hz_w  = (const float*)d_in[10];
    const float* tg_hz_b  = (const float*)d_in[11];
    const float* tp_ih_w  = (const float*)d_in[12];
    const float* tp_ih_b  = (const float*)d_in[13];
    const float* tp_hz_w  = (const float*)d_in[14];
    const float* tp_hz_b  = (const float*)d_in[15];
    const float* tl_w     = (const float*)d_in[16];
    const float* tl_b     = (const float*)d_in[17];
    const float* ts_w     = (const float*)d_in[18];
    const float* ts_b     = (const float*)d_in[19];
    const float* og_ih_w  = (const float*)d_in[20];
    const float* og_ih_b  = (const float*)d_in[21];
    const float* og_hz_w  = (const float*)d_in[22];
    const float* og_hz_b  = (const float*)d_in[23];
    const float* op_ih_w  = (const float*)d_in[24];
    const float* op_ih_b  = (const float*)d_in[25];
    const float* op_hz_w  = (const float*)d_in[26];
    const float* op_hz_b  = (const float*)d_in[27];
    const float* ol_w     = (const float*)d_in[28];
    const float* ol_b     = (const float*)d_in[29];
    const float* os_w     = (const float*)d_in[30];
    const float* os_b     = (const float*)d_in[31];
    float* out = (float*)d_out;

    phase1_kernel<<<G1, NTH>>>(eps, z0, h0,
        gru_w_ih, gru_b_ih, gru_w_hh, gru_b_hh,
        tg_ih_w, tg_ih_b, tg_hz_w, tg_hz_b,
        tp_ih_w, tp_ih_b, tp_hz_w, tp_hz_b,
        tl_w, tl_b, ts_w, ts_b);
    phase2_kernel<<<(NT * NB) / R2, 256>>>(
        og_ih_w, og_ih_b, og_hz_w, og_hz_b,
        op_ih_w, op_ih_b, op_hz_w, op_hz_b,
        ol_w, ol_b, os_w, os_b, out);
}

// round 9
// speedup vs baseline: 3.2697x; 1.3520x over previous
#include <cuda_runtime.h>
#include <cuda_bf16.h>
#include <math.h>

#define NB 512
#define NT 256
#define NZ 128
#define NX 64
#define NR 1024
#define G1B 592         // persistent grid: 4 blocks/SM on 148 SMs, all co-resident
#define NTH1 128
#define R2 16           // phase-2 rows per block

// ---------------- device scratch (static: no allocation allowed) ----------------
__device__ __align__(16) float    g_h[NB * NR];          // fp32 recurrence carry
__device__ __align__(16) unsigned g_hbf[NB * 512];       // bf16x2 of h   [512][512w]
__device__ __align__(16) unsigned g_zbf[NB * 64];        // bf16x2 of z   [512][64w]
__device__ __align__(16) float    g_rz[NB * 2048];
__device__ __align__(16) float    g_in[NB * NR];
__device__ __align__(16) float    g_hn[NB * NR];
__device__ __align__(16) unsigned g_hidbf[NB * 1024];    // bf16x2 relu(hid) [512][1024w]
__device__ __align__(16) float    g_loclin[NB * NZ];
__device__ __align__(16) float    g_gp[4 * NB * NZ];
__device__ __align__(16) float    g_pp[4 * NB * NZ];
__device__ __align__(16) float    g_zall[(size_t)NT * NB * NZ];  // [T,B,Z] fp32
// bf16 weight copies (converted once per launch), word = bf16x2 along K
__device__ __align__(16) unsigned g_wihb[3072 * 64];
__device__ __align__(16) unsigned g_whhb[3072 * 512];
__device__ __align__(16) unsigned g_tgwb[1024 * 512];
__device__ __align__(16) unsigned g_tpwb[1024 * 512];
__device__ __align__(16) unsigned g_tghwb[NZ * 512];
__device__ __align__(16) unsigned g_tphwb[NZ * 512];
__device__ __align__(16) unsigned g_tlwb[NZ * 512];
__device__ unsigned g_bar;   // zero-init; monotonic tickets, never reset

// ---------------- helpers ----------------
__device__ __forceinline__ float sigm(float x) { return 1.0f / (1.0f + expf(-x)); }
__device__ __forceinline__ float softplus_f(float x) {
    return fmaxf(x, 0.0f) + log1pf(expf(-fabsf(x)));
}
__device__ __forceinline__ unsigned packbf(float lo, float hi) {
    unsigned r;
    asm("cvt.rn.bf16x2.f32 %0, %1, %2;" : "=r"(r) : "f"(hi), "f"(lo));
    return r;
}
__device__ __forceinline__ void mma_bf16(float c[4],
    unsigned a0, unsigned a1, unsigned a2, unsigned a3, unsigned b0, unsigned b1)
{
    asm volatile(
        "mma.sync.aligned.m16n8k16.row.col.f32.bf16.bf16.f32 "
        "{%0,%1,%2,%3},{%4,%5,%6,%7},{%8,%9},{%0,%1,%2,%3};"
        : "+f"(c[0]), "+f"(c[1]), "+f"(c[2]), "+f"(c[3])
        : "r"(a0), "r"(a1), "r"(a2), "r"(a3), "r"(b0), "r"(b1));
}
// XOR swizzle: 64 rows x 32 words, banks conflict-free for frag LDS and STS.128
__device__ __forceinline__ int swz(int row, int w) {
    return (row << 5) + (w ^ ((row & 7) << 2));
}

// Software grid barrier (monotonic tickets)
__device__ __forceinline__ void gbar() {
    __syncthreads();
    if (threadIdx.x == 0) {
        __threadfence();
        unsigned t = atomicAdd(&g_bar, 1u);
        unsigned tgt = (t / G1B + 1u) * G1B;
        while (*((volatile unsigned*)&g_bar) < tgt) { }
    }
    __syncthreads();
}

// ---- bf16 TC tile worker: block 64x64, 4 warps of 32x32, BK=64 ----
// c[mi][nj][0..3] m16n8 frags. A rows bm.., W rows bn.. (K-contig bf16x2 words)
__device__ __forceinline__ void mm_bf(float c[2][4][4],
    const unsigned* __restrict__ A, int ldaw,
    const unsigned* __restrict__ W, int ldww, int K,
    int bm, int bn, unsigned* As, unsigned* Ws)
{
    const int tid = threadIdx.x;
    const int lane = tid & 31, wid = tid >> 5;
    const int m_off = (wid & 1) << 5, n_off = (wid >> 1) << 5;
    const int gq = lane >> 2, l4 = lane & 3;
    const int srow = tid >> 1, shalf = (tid & 1) << 4;
    const int d0 = swz(srow, shalf), d1 = swz(srow, shalf + 4),
              d2 = swz(srow, shalf + 8), d3 = swz(srow, shalf + 12);
    const int nch = K >> 6;
    const unsigned* Arow = A + (size_t)(bm + srow) * ldaw + shalf;
    const unsigned* Wrow = W + (size_t)(bn + srow) * ldww + shalf;

    for (int ch = 0; ch < nch; ch++) {
        uint4 va0 = __ldcg((const uint4*)(Arow + ch * 32));
        uint4 va1 = __ldcg((const uint4*)(Arow + ch * 32 + 4));
        uint4 va2 = __ldcg((const uint4*)(Arow + ch * 32 + 8));
        uint4 va3 = __ldcg((const uint4*)(Arow + ch * 32 + 12));
        uint4 vw0 = __ldg((const uint4*)(Wrow + ch * 32));
        uint4 vw1 = __ldg((const uint4*)(Wrow + ch * 32 + 4));
        uint4 vw2 = __ldg((const uint4*)(Wrow + ch * 32 + 8));
        uint4 vw3 = __ldg((const uint4*)(Wrow + ch * 32 + 12));
        *(uint4*)&As[d0] = va0; *(uint4*)&As[d1] = va1;
        *(uint4*)&As[d2] = va2; *(uint4*)&As[d3] = va3;
        *(uint4*)&Ws[d0] = vw0; *(uint4*)&Ws[d1] = vw1;
        *(uint4*)&Ws[d2] = vw2; *(uint4*)&Ws[d3] = vw3;
        __syncthreads();
#pragma unroll
        for (int ks = 0; ks < 4; ks++) {
            const int kb = ks << 3;
            unsigned a[2][4], b[4][2];
#pragma unroll
            for (int mi = 0; mi < 2; mi++) {
                int r0 = m_off + (mi << 4) + gq;
                a[mi][0] = As[swz(r0,     kb + l4)];
                a[mi][1] = As[swz(r0 + 8, kb + l4)];
                a[mi][2] = As[swz(r0,     kb + l4 + 4)];
                a[mi][3] = As[swz(r0 + 8, kb + l4 + 4)];
            }
#pragma unroll
            for (int nj = 0; nj < 4; nj++) {
                int rn = n_off + (nj << 3) + gq;
                b[nj][0] = Ws[swz(rn, kb + l4)];
                b[nj][1] = Ws[swz(rn, kb + l4 + 4)];
            }
#pragma unroll
            for (int mi = 0; mi < 2; mi++)
#pragma unroll
                for (int nj = 0; nj < 4; nj++)
                    mma_bf16(c[mi][nj], a[mi][0], a[mi][1], a[mi][2], a[mi][3],
                             b[nj][0], b[nj][1]);
        }
        __syncthreads();
    }
}

// ---------------- phase 1: whole recurrence in ONE persistent kernel --------
__global__ void __launch_bounds__(NTH1, 4) phase1_kernel(
    const float* __restrict__ eps,
    const float* __restrict__ z0,   const float* __restrict__ h0,
    const float* __restrict__ w_ih, const float* __restrict__ b_ih,
    const float* __restrict__ w_hh, const float* __restrict__ b_hh,
    const float* __restrict__ tgw,  const float* __restrict__ tgb,
    const float* __restrict__ tghw, const float* __restrict__ tghb,
    const float* __restrict__ tpw,  const float* __restrict__ tpb,
    const float* __restrict__ tphw, const float* __restrict__ tphb,
    const float* __restrict__ tlw,  const float* __restrict__ tlb,
    const float* __restrict__ tsw,  const float* __restrict__ tsb)
{
    __shared__ __align__(16) unsigned As[2048];
    __shared__ __align__(16) unsigned Ws[2048];
    const int bid = blockIdx.x, tid = threadIdx.x;
    const int lane = tid & 31, wid = tid >> 5;
    const int m_off = (wid & 1) << 5, n_off = (wid >> 1) << 5;
    const int gq = lane >> 2, l4 = lane & 3;
    const int gidx = bid * NTH1 + tid, gstride = G1B * NTH1;

    // ---- per-launch init: bf16 weight copies + state ----
    for (int i = gidx; i < 3072 * 64;  i += gstride) g_wihb[i]  = packbf(w_ih[2*i], w_ih[2*i+1]);
    for (int i = gidx; i < 3072 * 512; i += gstride) g_whhb[i]  = packbf(w_hh[2*i], w_hh[2*i+1]);
    for (int i = gidx; i < 1024 * 512; i += gstride) g_tgwb[i]  = packbf(tgw[2*i], tgw[2*i+1]);
    for (int i = gidx; i < 1024 * 512; i += gstride) g_tpwb[i]  = packbf(tpw[2*i], tpw[2*i+1]);
    for (int i = gidx; i < NZ * 512;   i += gstride) g_tghwb[i] = packbf(tghw[2*i], tghw[2*i+1]);
    for (int i = gidx; i < NZ * 512;   i += gstride) g_tphwb[i] = packbf(tphw[2*i], tphw[2*i+1]);
    for (int i = gidx; i < NZ * 512;   i += gstride) g_tlwb[i]  = packbf(tlw[2*i], tlw[2*i+1]);
    for (int i = gidx; i < NB * 512;   i += gstride) {
        float v0 = h0[(2*i) & (NR-1)], v1 = h0[(2*i+1) & (NR-1)];
        *(float2*)&g_h[2*i] = make_float2(v0, v1);
        g_hbf[i] = packbf(v0, v1);
    }
    for (int i = gidx; i < NB * 64;    i += gstride)
        g_zbf[i] = packbf(z0[(2*i) & (NZ-1)], z0[(2*i+1) & (NZ-1)]);
    gbar();

    for (int t = 0; t < NT; t++) {
        // ---- S1: GRU gate pre-activations [512,3072], K = 1024(h)+128(z) ----
        for (int tile = bid; tile < 384; tile += G1B) {
            int nt = tile / 8, mt = tile & 7;
            int bm = mt << 6, bn = nt << 6;
            float c[2][4][4] = {};
            if (nt < 32) {      // r,z columns: gi+gh summed
                mm_bf(c, g_hbf, 512, g_whhb, 512, NR, bm, bn, As, Ws);
                mm_bf(c, g_zbf, 64,  g_wihb, 64,  NZ, bm, bn, As, Ws);
#pragma unroll
                for (int mi = 0; mi < 2; mi++) {
                    int er = bm + m_off + (mi << 4) + gq;
#pragma unroll
                    for (int nj = 0; nj < 4; nj++) {
                        int cn = bn + n_off + (nj << 3) + (l4 << 1);
                        float b0 = b_ih[cn] + b_hh[cn], b1 = b_ih[cn+1] + b_hh[cn+1];
                        *(float2*)&g_rz[er * 2048 + cn]       = make_float2(c[mi][nj][0] + b0, c[mi][nj][1] + b1);
                        *(float2*)&g_rz[(er + 8) * 2048 + cn] = make_float2(c[mi][nj][2] + b0, c[mi][nj][3] + b1);
                    }
                }
            } else {            // n columns: i_n and h_n separately
                mm_bf(c, g_zbf, 64, g_wihb, 64, NZ, bm, bn, As, Ws);
#pragma unroll
                for (int mi = 0; mi < 2; mi++) {
                    int er = bm + m_off + (mi << 4) + gq;
#pragma unroll
                    for (int nj = 0; nj < 4; nj++) {
                        int cn = bn + n_off + (nj << 3) + (l4 << 1);
                        int nn = cn - 2048;
                        *(float2*)&g_in[er * 1024 + nn]       = make_float2(c[mi][nj][0] + b_ih[cn], c[mi][nj][1] + b_ih[cn+1]);
                        *(float2*)&g_in[(er + 8) * 1024 + nn] = make_float2(c[mi][nj][2] + b_ih[cn], c[mi][nj][3] + b_ih[cn+1]);
                        c[mi][nj][0] = c[mi][nj][1] = c[mi][nj][2] = c[mi][nj][3] = 0.0f;
                    }
                }
                mm_bf(c, g_hbf, 512, g_whhb, 512, NR, bm, bn, As, Ws);
#pragma unroll
                for (int mi = 0; mi < 2; mi++) {
                    int er = bm + m_off + (mi << 4) + gq;
#pragma unroll
                    for (int nj = 0; nj < 4; nj++) {
                        int cn = bn + n_off + (nj << 3) + (l4 << 1);
                        int nn = cn - 2048;
                        *(float2*)&g_hn[er * 1024 + nn]       = make_float2(c[mi][nj][0] + b_hh[cn], c[mi][nj][1] + b_hh[cn+1]);
                        *(float2*)&g_hn[(er + 8) * 1024 + nn] = make_float2(c[mi][nj][2] + b_hh[cn], c[mi][nj][3] + b_hh[cn+1]);
                    }
                }
            }
        }
        gbar();
        // ---- S2: GRU nonlinearity -> h_new (fp32 carry + bf16 pack) ----
        for (int idx = gidx; idx < NB * 512; idx += gstride) {
            int b = idx >> 9, w = idx & 511;
            int j = w << 1;
            float r0 = sigm(__ldcg(&g_rz[b * 2048 + j]));
            float r1 = sigm(__ldcg(&g_rz[b * 2048 + j + 1]));
            float zz0 = sigm(__ldcg(&g_rz[b * 2048 + 1024 + j]));
            float zz1 = sigm(__ldcg(&g_rz[b * 2048 + 1024 + j + 1]));
            float2 inv = __ldcg((const float2*)&g_in[b * 1024 + j]);
            float2 hnv = __ldcg((const float2*)&g_hn[b * 1024 + j]);
            float2 hp  = *(const float2*)&g_h[b * 1024 + j];
            float n0 = tanhf(inv.x + r0 * hnv.x);
            float n1 = tanhf(inv.y + r1 * hnv.y);
            float h0n = (1.0f - zz0) * n0 + zz0 * hp.x;
            float h1n = (1.0f - zz1) * n1 + zz1 * hp.y;
            *(float2*)&g_h[b * 1024 + j] = make_float2(h0n, h1n);
            g_hbf[idx] = packbf(h0n, h1n);
        }
        gbar();
        // ---- S3: hid = relu(h@[tgw;tpw]^T+b) [512,2048] + loclin [512,128] ----
        for (int tile = bid; tile < 272; tile += G1B) {
            float c[2][4][4] = {};
            if (tile < 256) {
                int nt = tile / 8, mt = tile & 7;
                int bm = mt << 6, bn = nt << 6;
                const unsigned* Wm; const float* bb; int nl;
                if (bn < 1024) { Wm = g_tgwb; bb = tgb; nl = bn; }
                else           { Wm = g_tpwb; bb = tpb; nl = bn - 1024; }
                mm_bf(c, g_hbf, 512, Wm, 512, NR, bm, nl, As, Ws);
#pragma unroll
                for (int mi = 0; mi < 2; mi++) {
                    int er = bm + m_off + (mi << 4) + gq;
#pragma unroll
                    for (int nj = 0; nj < 4; nj++) {
                        int lc = n_off + (nj << 3) + (l4 << 1);
                        float b0 = bb[nl + lc], b1 = bb[nl + lc + 1];
                        int wcol = ((bn + n_off + (nj << 3)) >> 1) + l4;
                        g_hidbf[er * 1024 + wcol] =
                            packbf(fmaxf(c[mi][nj][0] + b0, 0.0f), fmaxf(c[mi][nj][1] + b1, 0.0f));
                        g_hidbf[(er + 8) * 1024 + wcol] =
                            packbf(fmaxf(c[mi][nj][2] + b0, 0.0f), fmaxf(c[mi][nj][3] + b1, 0.0f));
                    }
                }
            } else {
                int t2 = tile - 256;              // 0..15: loclin 8m x 2n
                int bm = (t2 >> 1) << 6, bn = (t2 & 1) << 6;
                mm_bf(c, g_hbf, 512, g_tlwb, 512, NR, bm, bn, As, Ws);
#pragma unroll
                for (int mi = 0; mi < 2; mi++) {
                    int er = bm + m_off + (mi << 4) + gq;
#pragma unroll
                    for (int nj = 0; nj < 4; nj++) {
                        int cn = bn + n_off + (nj << 3) + (l4 << 1);
                        *(float2*)&g_loclin[er * 128 + cn]       = make_float2(c[mi][nj][0] + tlb[cn], c[mi][nj][1] + tlb[cn+1]);
                        *(float2*)&g_loclin[(er + 8) * 128 + cn] = make_float2(c[mi][nj][2] + tlb[cn], c[mi][nj][3] + tlb[cn+1]);
                    }
                }
            }
        }
        gbar();
        // ---- S4: gatep/prop [512,128] K=1024 k-split4 (128 tiles) ----
        for (int tile = bid; tile < 128; tile += G1B) {
            int gg = tile >> 6;
            int rem = tile & 63;
            int ks = rem & 3, nt = (rem >> 2) & 1, mt = rem >> 3;
            int bm = mt << 6, bn = nt << 6;
            const unsigned* Aq = g_hidbf + (gg ? 512 : 0) + (ks << 7);
            const unsigned* Wq = (gg ? g_tphwb : g_tghwb) + (ks << 7);
            float c[2][4][4] = {};
            mm_bf(c, Aq, 1024, Wq, 512, 256, bm, bn, As, Ws);
            float* dst = (gg ? g_pp : g_gp) + ks * (NB * NZ);
#pragma unroll
            for (int mi = 0; mi < 2; mi++) {
                int er = bm + m_off + (mi << 4) + gq;
#pragma unroll
                for (int nj = 0; nj < 4; nj++) {
                    int cn = bn + n_off + (nj << 3) + (l4 << 1);
                    *(float2*)&dst[er * 128 + cn]       = make_float2(c[mi][nj][0], c[mi][nj][1]);
                    *(float2*)&dst[(er + 8) * 128 + cn] = make_float2(c[mi][nj][2], c[mi][nj][3]);
                }
            }
        }
        gbar();
        // ---- S5: finalize z_t (reduce + fused scale GEMV + reparam), fp32 ----
        if (bid < NB) {
            int b = bid, i = tid;   // 128 threads = z dim
            float* rp   = (float*)As;          // [128]
            float* zrow = (float*)(As + 128);  // [128]
            float gp = tghb[i], pp = tphb[i];
#pragma unroll
            for (int ks = 0; ks < 4; ks++) {
                gp += __ldcg(&g_gp[ks * (NB * NZ) + b * 128 + i]);
                pp += __ldcg(&g_pp[ks * (NB * NZ) + b * 128 + i]);
            }
            rp[i] = fmaxf(pp, 0.0f);
            __syncthreads();
            float s = tsb[i];
            const float* wr = tsw + (size_t)i * 128;
#pragma unroll 8
            for (int j = 0; j < 128; j += 4) {
                float4 w = *(const float4*)(wr + j);
                s += rp[j] * w.x + rp[j+1] * w.y + rp[j+2] * w.z + rp[j+3] * w.w;
            }
            float gate = sigm(gp);
            float loc = (1.0f - gate) * __ldcg(&g_loclin[b * 128 + i]) + gate * pp;
            float zv = loc + softplus_f(s) * eps[((size_t)b * NT + t) * NZ + i];
            zrow[i] = zv;
            g_zall[((size_t)t * NB + b) * NZ + i] = zv;
            __syncthreads();
            if (i < 64) g_zbf[b * 64 + i] = packbf(zrow[2*i], zrow[2*i+1]);
        }
        gbar();
    }
}

// ---------------- phase 2: obs transformer, fully fused per-row (fp32) --------
__device__ __forceinline__ void obs_path(float acc[4],
                                         const float* __restrict__ wih,
                                         const float* __restrict__ bih,
                                         const float* __restrict__ whz,
                                         float (*zs)[128], float (*hs)[512], int tid)
{
    const int i = tid & 63, rg = tid >> 6;
    for (int half = 0; half < 2; half++) {
        int u0 = half * 512 + tid * 2;
        const float* w0 = wih + (size_t)u0 * 128;
        const float* w1 = w0 + 128;
        float b0 = bih[u0], b1 = bih[u0 + 1];
        for (int rc = 0; rc < 2; rc++) {
            float a0[8], a1[8];
#pragma unroll
            for (int r = 0; r < 8; r++) { a0[r] = b0; a1[r] = b1; }
            for (int k = 0; k < 128; k += 4) {
                float4 wv0 = *(const float4*)(w0 + k);
                float4 wv1 = *(const float4*)(w1 + k);
#pragma unroll
                for (int r = 0; r < 8; r++) {
                    float4 zv = *(const float4*)&zs[rc * 8 + r][k];
                    a0[r] += zv.x * wv0.x + zv.y * wv0.y + zv.z * wv0.z + zv.w * wv0.w;
                    a1[r] += zv.x * wv1.x + zv.y * wv1.y + zv.z * wv1.z + zv.w * wv1.w;
                }
            }
            int uu = tid * 2;
#pragma unroll
            for (int r = 0; r < 8; r++) {
                hs[rc * 8 + r][uu]     = fmaxf(a0[r], 0.0f);
                hs[rc * 8 + r][uu + 1] = fmaxf(a1[r], 0.0f);
            }
        }
        __syncthreads();
        const float* wr = whz + (size_t)i * 1024 + half * 512;
        for (int k = 0; k < 512; k += 4) {
            float4 wv = *(const float4*)(wr + k);
#pragma unroll
            for (int r4 = 0; r4 < 4; r4++) {
                const float* h = &hs[rg * 4 + r4][k];
                acc[r4] += h[0] * wv.x + h[1] * wv.y + h[2] * wv.z + h[3] * wv.w;
            }
        }
        __syncthreads();
    }
}

__global__ void __launch_bounds__(256) phase2_kernel(
    const float* __restrict__ ogw, const float* __restrict__ ogb,
    const float* __restrict__ oghw, const float* __restrict__ oghb,
    const float* __restrict__ opw, const float* __restrict__ opb,
    const float* __restrict__ ophw, const float* __restrict__ ophb,
    const float* __restrict__ olw, const float* __restrict__ olb,
    const float* __restrict__ osw, const float* __restrict__ osb,
    float* __restrict__ out)
{
    __shared__ float zs[R2][128];
    __shared__ float hs[R2][512];
    const int tid = threadIdx.x;
    const size_t base = (size_t)blockIdx.x * R2;

    for (int idx = tid; idx < R2 * 128 / 4; idx += 256) {
        int r = idx >> 5, c = (idx & 31) << 2;
        *(float4*)&zs[r][c] = *(const float4*)&g_zall[(base + r) * 128 + c];
    }
    __syncthreads();

    const int i = tid & 63, rg = tid >> 6;
    float accg[4] = {0.f, 0.f, 0.f, 0.f};
    float accp[4] = {0.f, 0.f, 0.f, 0.f};
    obs_path(accg, ogw, ogb, oghw, zs, hs, tid);
    obs_path(accp, opw, opb, ophw, zs, hs, tid);

    float gate[4], prop[4];
    float (*ps)[64] = (float(*)[64])hs;
#pragma unroll
    for (int r4 = 0; r4 < 4; r4++) {
        gate[r4] = sigm(accg[r4] + oghb[i]);
        prop[r4] = accp[r4] + ophb[i];
        ps[rg * 4 + r4][i] = fmaxf(prop[r4], 0.0f);
    }
    __syncthreads();

    float s[4], loc[4];
#pragma unroll
    for (int r4 = 0; r4 < 4; r4++) { s[r4] = osb[i]; loc[r4] = olb[i]; }
    const float* wsr = osw + (size_t)i * 64;
    for (int j = 0; j < 64; j += 4) {
        float4 wv = *(const float4*)(wsr + j);
#pragma unroll
        for (int r4 = 0; r4 < 4; r4++) {
            const float* p = &ps[rg * 4 + r4][j];
            s[r4] += p[0] * wv.x + p[1] * wv.y + p[2] * wv.z + p[3] * wv.w;
        }
    }
    const float* wlr = olw + (size_t)i * 128;
    for (int k = 0; k < 128; k += 4) {
        float4 wv = *(const float4*)(wlr + k);
#pragma unroll
        for (int r4 = 0; r4 < 4; r4++) {
            float4 zv = *(const float4*)&zs[rg * 4 + r4][k];
            loc[r4] += zv.x * wv.x + zv.y * wv.y + zv.z * wv.z + zv.w * wv.w;
        }
    }
#pragma unroll
    for (int r4 = 0; r4 < 4; r4++) {
        size_t gr = base + rg * 4 + r4;
        int tt = (int)(gr >> 9);
        int bb = (int)(gr & 511);
        float lo = (1.0f - gate[r4]) * loc[r4] + gate[r4] * prop[r4];
        float sc = softplus_f(s[r4]);
        out[((size_t)bb * NT + tt) * 128 + i]      = lo;
        out[((size_t)bb * NT + tt) * 128 + 64 + i] = sc;
    }
}

// ---------------- host launcher: 2 graph nodes ----------------
extern "C" void kernel_launch(void* const* d_in, const int* in_sizes, int n_in,
                              void* d_out, int out_size)
{
    (void)in_sizes; (void)n_in; (void)out_size;
    const float* eps      = (const float*)d_in[1];
    const float* z0       = (const float*)d_in[2];
    const float* h0       = (const float*)d_in[3];
    const float* gru_w_ih = (const float*)d_in[4];
    const float* gru_b_ih = (const float*)d_in[5];
    const float* gru_w_hh = (const float*)d_in[6];
    const float* gru_b_hh = (const float*)d_in[7];
    const float* tg_ih_w  = (const float*)d_in[8];
    const float* tg_ih_b  = (const float*)d_in[9];
    const float* tg_hz_w  = (const float*)d_in[10];
    const float* tg_hz_b  = (const float*)d_in[11];
    const float* tp_ih_w  = (const float*)d_in[12];
    const float* tp_ih_b  = (const float*)d_in[13];
    const float* tp_hz_w  = (const float*)d_in[14];
    const float* tp_hz_b  = (const float*)d_in[15];
    const float* tl_w     = (const float*)d_in[16];
    const float* tl_b     = (const float*)d_in[17];
    const float* ts_w     = (const float*)d_in[18];
    const float* ts_b     = (const float*)d_in[19];
    const float* og_ih_w  = (const float*)d_in[20];
    const float* og_ih_b  = (const float*)d_in[21];
    const float* og_hz_w  = (const float*)d_in[22];
    const float* og_hz_b  = (const float*)d_in[23];
    const float* op_ih_w  = (const float*)d_in[24];
    const float* op_ih_b  = (const float*)d_in[25];
    const float* op_hz_w  = (const float*)d_in[26];
    const float* op_hz_b  = (const float*)d_in[27];
    const float* ol_w     = (const float*)d_in[28];
    const float* ol_b     = (const float*)d_in[29];
    const float* os_w     = (const float*)d_in[30];
    const float* os_b     = (const float*)d_in[31];
    float* out = (float*)d_out;

    phase1_kernel<<<G1B, NTH1>>>(eps, z0, h0,
        gru_w_ih, gru_b_ih, gru_w_hh, gru_b_hh,
        tg_ih_w, tg_ih_b, tg_hz_w, tg_hz_b,
        tp_ih_w, tp_ih_b, tp_hz_w, tp_hz_b,
        tl_w, tl_b, ts_w, ts_b);
    phase2_kernel<<<(NT * NB) / R2, 256>>>(
        og_ih_w, og_ih_b, og_hz_w, og_hz_b,
        op_ih_w, op_ih_b, op_hz_w, op_hz_b,
        ol_w, ol_b, os_w, os_b, out);
}

// round 12
// speedup vs baseline: 3.9319x; 1.2025x over previous
#include <cuda_runtime.h>
#include <cuda_bf16.h>
#include <math.h>

#define NB 512
#define NT 256
#define NZ 128
#define NX 64
#define NR 1024
#define G1B 592         // persistent grid: 4 blocks/SM on 148 SMs, all co-resident
#define NTH1 128

// ---------------- device scratch (static: no allocation allowed) ----------------
__device__ __align__(16) float    g_h[NB * NR];          // fp32 recurrence carry
__device__ __align__(16) unsigned g_hbf[NB * 512];       // bf16x2 of h   [512][512w]
__device__ __align__(16) unsigned g_zbf[NB * 64];        // bf16x2 of z   [512][64w]
__device__ __align__(16) float    g_rz[NB * 2048];
__device__ __align__(16) float    g_in[NB * NR];
__device__ __align__(16) float    g_hn[NB * NR];
__device__ __align__(16) unsigned g_hidbf[NB * 1024];    // bf16x2 relu(hid) [512][1024w]
__device__ __align__(16) float    g_loclin[NB * NZ];
__device__ __align__(16) float    g_gp[4 * NB * NZ];
__device__ __align__(16) float    g_pp[4 * NB * NZ];
__device__ __align__(16) float    g_zall[(size_t)NT * NB * NZ];  // [T,B,Z] fp32
// bf16 weight copies (converted once per launch), word = bf16x2 along K
__device__ __align__(16) unsigned g_wihb[3072 * 64];
__device__ __align__(16) unsigned g_whhb[3072 * 512];
__device__ __align__(16) unsigned g_tgwb[1024 * 512];
__device__ __align__(16) unsigned g_tpwb[1024 * 512];
__device__ __align__(16) unsigned g_tghwb[NZ * 512];
__device__ __align__(16) unsigned g_tphwb[NZ * 512];
__device__ __align__(16) unsigned g_tlwb[NZ * 512];
__device__ unsigned g_bar;   // zero-init; monotonic tickets, never reset

// ---------------- helpers ----------------
__device__ __forceinline__ float sigm(float x) { return 1.0f / (1.0f + expf(-x)); }
__device__ __forceinline__ float softplus_f(float x) {
    return fmaxf(x, 0.0f) + log1pf(expf(-fabsf(x)));
}
__device__ __forceinline__ unsigned packbf(float lo, float hi) {
    unsigned r;
    asm("cvt.rn.bf16x2.f32 %0, %1, %2;" : "=r"(r) : "f"(hi), "f"(lo));
    return r;
}
__device__ __forceinline__ void mma_bf16(float c[4],
    unsigned a0, unsigned a1, unsigned a2, unsigned a3, unsigned b0, unsigned b1)
{
    asm volatile(
        "mma.sync.aligned.m16n8k16.row.col.f32.bf16.bf16.f32 "
        "{%0,%1,%2,%3},{%4,%5,%6,%7},{%8,%9},{%0,%1,%2,%3};"
        : "+f"(c[0]), "+f"(c[1]), "+f"(c[2]), "+f"(c[3])
        : "r"(a0), "r"(a1), "r"(a2), "r"(a3), "r"(b0), "r"(b1));
}
// XOR swizzle: 64 rows x 32 words, banks conflict-free for frag LDS and cp.async STS
__device__ __forceinline__ int swz(int row, int w) {
    return (row << 5) + (w ^ ((row & 7) << 2));
}
__device__ __forceinline__ void cpa16(unsigned saddr, const void* g) {
    asm volatile("cp.async.cg.shared.global [%0], [%1], 16;" :: "r"(saddr), "l"(g));
}
#define CP_COMMIT() asm volatile("cp.async.commit_group;" ::: "memory")
#define CP_WAIT1()  asm volatile("cp.async.wait_group 1;" ::: "memory")
#define CP_WAIT0()  asm volatile("cp.async.wait_group 0;" ::: "memory")

// Software grid barrier (monotonic tickets; nanosleep backoff on the spin)
__device__ __forceinline__ void gbar() {
    __syncthreads();
    if (threadIdx.x == 0) {
        __threadfence();
        unsigned t = atomicAdd(&g_bar, 1u);
        unsigned tgt = (t / G1B + 1u) * G1B;
        while (*((volatile unsigned*)&g_bar) < tgt) { __nanosleep(64); }
    }
    __syncthreads();
}

// ---- bf16 TC tile worker: block 64x64, 4 warps of 32x32, BK=64 ----
// cp.async double-buffered: chunk c+1 staged while chunk c computes.
// Smem layout (words): [0..2047] A buf0, [2048..4095] A buf1,
//                      [4096..6143] W buf0, [6144..8191] W buf1.
__device__ __forceinline__ void mm_bf(float c[2][4][4],
    const unsigned* __restrict__ A, int ldaw,
    const unsigned* __restrict__ W, int ldww, int K,
    int bm, int bn, unsigned* Sm, unsigned smb)
{
    const int tid = threadIdx.x;
    const int lane = tid & 31, wid = tid >> 5;
    const int m_off = (wid & 1) << 5, n_off = (wid >> 1) << 5;
    const int gq = lane >> 2, l4 = lane & 3;
    const int srow = tid >> 1, shalf = (tid & 1) << 4;
    const int d0 = swz(srow, shalf) << 2, d1 = swz(srow, shalf + 4) << 2,
              d2 = swz(srow, shalf + 8) << 2, d3 = swz(srow, shalf + 12) << 2;
    const unsigned* Arow = A + (size_t)(bm + srow) * ldaw + shalf;
    const unsigned* Wrow = W + (size_t)(bn + srow) * ldww + shalf;
    const int nch = K >> 6;

    // stage chunk 0 -> buffer 0
    {
        unsigned ab = smb, wb = smb + 16384;
        cpa16(ab + d0, Arow);     cpa16(ab + d1, Arow + 4);
        cpa16(ab + d2, Arow + 8); cpa16(ab + d3, Arow + 12);
        cpa16(wb + d0, Wrow);     cpa16(wb + d1, Wrow + 4);
        cpa16(wb + d2, Wrow + 8); cpa16(wb + d3, Wrow + 12);
        CP_COMMIT();
    }
    for (int ch = 0; ch < nch; ch++) {
        if (ch + 1 < nch) {
            unsigned ab = smb + (((ch + 1) & 1) << 13);
            unsigned wb = ab + 16384;
            const unsigned* Ar = Arow + (ch + 1) * 32;
            const unsigned* Wr = Wrow + (ch + 1) * 32;
            cpa16(ab + d0, Ar);     cpa16(ab + d1, Ar + 4);
            cpa16(ab + d2, Ar + 8); cpa16(ab + d3, Ar + 12);
            cpa16(wb + d0, Wr);     cpa16(wb + d1, Wr + 4);
            cpa16(wb + d2, Wr + 8); cpa16(wb + d3, Wr + 12);
            CP_COMMIT();
            CP_WAIT1();
        } else {
            CP_WAIT0();
        }
        __syncthreads();
        const unsigned* Ab = Sm + ((ch & 1) << 11);
        const unsigned* Wb = Sm + 4096 + ((ch & 1) << 11);
#pragma unroll
        for (int ks = 0; ks < 4; ks++) {
            const int kb = ks << 3;
            unsigned a[2][4], b[4][2];
#pragma unroll
            for (int mi = 0; mi < 2; mi++) {
                int r0 = m_off + (mi << 4) + gq;
                a[mi][0] = Ab[swz(r0,     kb + l4)];
                a[mi][1] = Ab[swz(r0 + 8, kb + l4)];
                a[mi][2] = Ab[swz(r0,     kb + l4 + 4)];
                a[mi][3] = Ab[swz(r0 + 8, kb + l4 + 4)];
            }
#pragma unroll
            for (int nj = 0; nj < 4; nj++) {
                int rn = n_off + (nj << 3) + gq;
                b[nj][0] = Wb[swz(rn, kb + l4)];
                b[nj][1] = Wb[swz(rn, kb + l4 + 4)];
            }
#pragma unroll
            for (int mi = 0; mi < 2; mi++)
#pragma unroll
                for (int nj = 0; nj < 4; nj++)
                    mma_bf16(c[mi][nj], a[mi][0], a[mi][1], a[mi][2], a[mi][3],
                             b[nj][0], b[nj][1]);
        }
        __syncthreads();
    }
}

// phase-2 hidden-path helper (128 threads, 8 rows): acc += contribution to
// output col i (=tid&63) for 4 rows of group rg (=tid>>6)
__device__ __forceinline__ void obs_path8(float acc[4],
    const float* __restrict__ wih, const float* __restrict__ bih,
    const float* __restrict__ whz, float* zs, float* hs, int tid)
{
    const int i = tid & 63, rg = tid >> 6;
    for (int half = 0; half < 2; half++) {
        int u0 = half * 512 + tid * 4;
        float a[4][8];
#pragma unroll
        for (int q = 0; q < 4; q++) {
            float bq = bih[u0 + q];
#pragma unroll
            for (int r = 0; r < 8; r++) a[q][r] = bq;
        }
        const float* w0 = wih + (size_t)u0 * 128;
        for (int k = 0; k < 128; k += 4) {
            float4 wv0 = *(const float4*)(w0 + k);
            float4 wv1 = *(const float4*)(w0 + 128 + k);
            float4 wv2 = *(const float4*)(w0 + 256 + k);
            float4 wv3 = *(const float4*)(w0 + 384 + k);
#pragma unroll
            for (int r = 0; r < 8; r++) {
                float4 zv = *(const float4*)&zs[r * 128 + k];
                a[0][r] += zv.x * wv0.x + zv.y * wv0.y + zv.z * wv0.z + zv.w * wv0.w;
                a[1][r] += zv.x * wv1.x + zv.y * wv1.y + zv.z * wv1.z + zv.w * wv1.w;
                a[2][r] += zv.x * wv2.x + zv.y * wv2.y + zv.z * wv2.z + zv.w * wv2.w;
                a[3][r] += zv.x * wv3.x + zv.y * wv3.y + zv.z * wv3.z + zv.w * wv3.w;
            }
        }
#pragma unroll
        for (int r = 0; r < 8; r++)
            *(float4*)&hs[r * 512 + tid * 4] =
                make_float4(fmaxf(a[0][r], 0.f), fmaxf(a[1][r], 0.f),
                            fmaxf(a[2][r], 0.f), fmaxf(a[3][r], 0.f));
        __syncthreads();
        const float* wr = whz + (size_t)i * 1024 + half * 512;
        for (int k = 0; k < 512; k += 4) {
            float4 wv = *(const float4*)(wr + k);
#pragma unroll
            for (int r4 = 0; r4 < 4; r4++) {
                const float* h = &hs[(rg * 4 + r4) * 512 + k];
                acc[r4] += h[0] * wv.x + h[1] * wv.y + h[2] * wv.z + h[3] * wv.w;
            }
        }
        __syncthreads();
    }
}

// ---------------- THE kernel: init + recurrence + obs, one launch ----------------
__global__ void __launch_bounds__(NTH1, 4) ssm_kernel(
    const float* __restrict__ eps,
    const float* __restrict__ z0,   const float* __restrict__ h0,
    const float* __restrict__ w_ih, const float* __restrict__ b_ih,
    const float* __restrict__ w_hh, const float* __restrict__ b_hh,
    const float* __restrict__ tgw,  const float* __restrict__ tgb,
    const float* __restrict__ tghw, const float* __restrict__ tghb,
    const float* __restrict__ tpw,  const float* __restrict__ tpb,
    const float* __restrict__ tphw, const float* __restrict__ tphb,
    const float* __restrict__ tlw,  const float* __restrict__ tlb,
    const float* __restrict__ tsw,  const float* __restrict__ tsb,
    const float* __restrict__ ogw,  const float* __restrict__ ogb,
    const float* __restrict__ oghw, const float* __restrict__ oghb,
    const float* __restrict__ opw,  const float* __restrict__ opb,
    const float* __restrict__ ophw, const float* __restrict__ ophb,
    const float* __restrict__ olw,  const float* __restrict__ olb,
    const float* __restrict__ osw,  const float* __restrict__ osb,
    float* __restrict__ out)
{
    __shared__ __align__(16) unsigned Sm[8192];   // 32 KB: GEMM bufs / phase2 zs+hs
    const int bid = blockIdx.x, tid = threadIdx.x;
    const int lane = tid & 31, wid = tid >> 5;
    const int m_off = (wid & 1) << 5, n_off = (wid >> 1) << 5;
    const int gq = lane >> 2, l4 = lane & 3;
    const int gidx = bid * NTH1 + tid, gstride = G1B * NTH1;
    const unsigned smb = (unsigned)__cvta_generic_to_shared(Sm);

    // ---- per-launch init: bf16 weight copies + state ----
    for (int i = gidx; i < 3072 * 64;  i += gstride) g_wihb[i]  = packbf(w_ih[2*i], w_ih[2*i+1]);
    for (int i = gidx; i < 3072 * 512; i += gstride) g_whhb[i]  = packbf(w_hh[2*i], w_hh[2*i+1]);
    for (int i = gidx; i < 1024 * 512; i += gstride) g_tgwb[i]  = packbf(tgw[2*i], tgw[2*i+1]);
    for (int i = gidx; i < 1024 * 512; i += gstride) g_tpwb[i]  = packbf(tpw[2*i], tpw[2*i+1]);
    for (int i = gidx; i < NZ * 512;   i += gstride) g_tghwb[i] = packbf(tghw[2*i], tghw[2*i+1]);
    for (int i = gidx; i < NZ * 512;   i += gstride) g_tphwb[i] = packbf(tphw[2*i], tphw[2*i+1]);
    for (int i = gidx; i < NZ * 512;   i += gstride) g_tlwb[i]  = packbf(tlw[2*i], tlw[2*i+1]);
    for (int i = gidx; i < NB * 512;   i += gstride) {
        float v0 = h0[(2*i) & (NR-1)], v1 = h0[(2*i+1) & (NR-1)];
        *(float2*)&g_h[2*i] = make_float2(v0, v1);
        g_hbf[i] = packbf(v0, v1);
    }
    for (int i = gidx; i < NB * 64;    i += gstride)
        g_zbf[i] = packbf(z0[(2*i) & (NZ-1)], z0[(2*i+1) & (NZ-1)]);
    gbar();

    for (int t = 0; t < NT; t++) {
        // ---- S1: GRU gate pre-activations [512,3072], K = 1024(h)+128(z) ----
        for (int tile = bid; tile < 384; tile += G1B) {
            int nt = tile / 8, mt = tile & 7;
            int bm = mt << 6, bn = nt << 6;
            float c[2][4][4] = {};
            if (nt < 32) {      // r,z columns: gi+gh summed
                mm_bf(c, g_hbf, 512, g_whhb, 512, NR, bm, bn, Sm, smb);
                mm_bf(c, g_zbf, 64,  g_wihb, 64,  NZ, bm, bn, Sm, smb);
#pragma unroll
                for (int mi = 0; mi < 2; mi++) {
                    int er = bm + m_off + (mi << 4) + gq;
#pragma unroll
                    for (int nj = 0; nj < 4; nj++) {
                        int cn = bn + n_off + (nj << 3) + (l4 << 1);
                        float b0 = b_ih[cn] + b_hh[cn], b1 = b_ih[cn+1] + b_hh[cn+1];
                        *(float2*)&g_rz[er * 2048 + cn]       = make_float2(c[mi][nj][0] + b0, c[mi][nj][1] + b1);
                        *(float2*)&g_rz[(er + 8) * 2048 + cn] = make_float2(c[mi][nj][2] + b0, c[mi][nj][3] + b1);
                    }
                }
            } else {            // n columns: i_n and h_n separately
                mm_bf(c, g_zbf, 64, g_wihb, 64, NZ, bm, bn, Sm, smb);
#pragma unroll
                for (int mi = 0; mi < 2; mi++) {
                    int er = bm + m_off + (mi << 4) + gq;
#pragma unroll
                    for (int nj = 0; nj < 4; nj++) {
                        int cn = bn + n_off + (nj << 3) + (l4 << 1);
                        int nn = cn - 2048;
                        *(float2*)&g_in[er * 1024 + nn]       = make_float2(c[mi][nj][0] + b_ih[cn], c[mi][nj][1] + b_ih[cn+1]);
                        *(float2*)&g_in[(er + 8) * 1024 + nn] = make_float2(c[mi][nj][2] + b_ih[cn], c[mi][nj][3] + b_ih[cn+1]);
                        c[mi][nj][0] = c[mi][nj][1] = c[mi][nj][2] = c[mi][nj][3] = 0.0f;
                    }
                }
                mm_bf(c, g_hbf, 512, g_whhb, 512, NR, bm, bn, Sm, smb);
#pragma unroll
                for (int mi = 0; mi < 2; mi++) {
                    int er = bm + m_off + (mi << 4) + gq;
#pragma unroll
                    for (int nj = 0; nj < 4; nj++) {
                        int cn = bn + n_off + (nj << 3) + (l4 << 1);
                        int nn = cn - 2048;
                        *(float2*)&g_hn[er * 1024 + nn]       = make_float2(c[mi][nj][0] + b_hh[cn], c[mi][nj][1] + b_hh[cn+1]);
                        *(float2*)&g_hn[(er + 8) * 1024 + nn] = make_float2(c[mi][nj][2] + b_hh[cn], c[mi][nj][3] + b_hh[cn+1]);
                    }
                }
            }
        }
        gbar();
        // ---- S2: GRU nonlinearity -> h_new (fp32 carry + bf16 pack) ----
        for (int idx = gidx; idx < NB * 512; idx += gstride) {
            int b = idx >> 9, w = idx & 511;
            int j = w << 1;
            float r0 = sigm(__ldcg(&g_rz[b * 2048 + j]));
            float r1 = sigm(__ldcg(&g_rz[b * 2048 + j + 1]));
            float zz0 = sigm(__ldcg(&g_rz[b * 2048 + 1024 + j]));
            float zz1 = sigm(__ldcg(&g_rz[b * 2048 + 1024 + j + 1]));
            float2 inv = __ldcg((const float2*)&g_in[b * 1024 + j]);
            float2 hnv = __ldcg((const float2*)&g_hn[b * 1024 + j]);
            float2 hp  = *(const float2*)&g_h[b * 1024 + j];
            float n0 = tanhf(inv.x + r0 * hnv.x);
            float n1 = tanhf(inv.y + r1 * hnv.y);
            float h0n = (1.0f - zz0) * n0 + zz0 * hp.x;
            float h1n = (1.0f - zz1) * n1 + zz1 * hp.y;
            *(float2*)&g_h[b * 1024 + j] = make_float2(h0n, h1n);
            g_hbf[idx] = packbf(h0n, h1n);
        }
        gbar();
        // ---- S3: hid = relu(h@[tgw;tpw]^T+b) [512,2048] + loclin [512,128] ----
        for (int tile = bid; tile < 272; tile += G1B) {
            float c[2][4][4] = {};
            if (tile < 256) {
                int nt = tile / 8, mt = tile & 7;
                int bm = mt << 6, bn = nt << 6;
                const unsigned* Wm; const float* bb; int nl;
                if (bn < 1024) { Wm = g_tgwb; bb = tgb; nl = bn; }
                else           { Wm = g_tpwb; bb = tpb; nl = bn - 1024; }
                mm_bf(c, g_hbf, 512, Wm, 512, NR, bm, nl, Sm, smb);
#pragma unroll
                for (int mi = 0; mi < 2; mi++) {
                    int er = bm + m_off + (mi << 4) + gq;
#pragma unroll
                    for (int nj = 0; nj < 4; nj++) {
                        int lc = n_off + (nj << 3) + (l4 << 1);
                        float b0 = bb[nl + lc], b1 = bb[nl + lc + 1];
                        int wcol = ((bn + n_off + (nj << 3)) >> 1) + l4;
                        g_hidbf[er * 1024 + wcol] =
                            packbf(fmaxf(c[mi][nj][0] + b0, 0.0f), fmaxf(c[mi][nj][1] + b1, 0.0f));
                        g_hidbf[(er + 8) * 1024 + wcol] =
                            packbf(fmaxf(c[mi][nj][2] + b0, 0.0f), fmaxf(c[mi][nj][3] + b1, 0.0f));
                    }
                }
            } else {
                int t2 = tile - 256;              // 0..15: loclin 8m x 2n
                int bm = (t2 >> 1) << 6, bn = (t2 & 1) << 6;
                mm_bf(c, g_hbf, 512, g_tlwb, 512, NR, bm, bn, Sm, smb);
#pragma unroll
                for (int mi = 0; mi < 2; mi++) {
                    int er = bm + m_off + (mi << 4) + gq;
#pragma unroll
                    for (int nj = 0; nj < 4; nj++) {
                        int cn = bn + n_off + (nj << 3) + (l4 << 1);
                        *(float2*)&g_loclin[er * 128 + cn]       = make_float2(c[mi][nj][0] + tlb[cn], c[mi][nj][1] + tlb[cn+1]);
                        *(float2*)&g_loclin[(er + 8) * 128 + cn] = make_float2(c[mi][nj][2] + tlb[cn], c[mi][nj][3] + tlb[cn+1]);
                    }
                }
            }
        }
        gbar();
        // ---- S4: gatep/prop [512,128] K=1024 k-split4 (128 tiles) ----
        for (int tile = bid; tile < 128; tile += G1B) {
            int gg = tile >> 6;
            int rem = tile & 63;
            int ks = rem & 3, nt = (rem >> 2) & 1, mt = rem >> 3;
            int bm = mt << 6, bn = nt << 6;
            const unsigned* Aq = g_hidbf + (gg ? 512 : 0) + (ks << 7);
            const unsigned* Wq = (gg ? g_tphwb : g_tghwb) + (ks << 7);
            float c[2][4][4] = {};
            mm_bf(c, Aq, 1024, Wq, 512, 256, bm, bn, Sm, smb);
            float* dst = (gg ? g_pp : g_gp) + ks * (NB * NZ);
#pragma unroll
            for (int mi = 0; mi < 2; mi++) {
                int er = bm + m_off + (mi << 4) + gq;
#pragma unroll
                for (int nj = 0; nj < 4; nj++) {
                    int cn = bn + n_off + (nj << 3) + (l4 << 1);
                    *(float2*)&dst[er * 128 + cn]       = make_float2(c[mi][nj][0], c[mi][nj][1]);
                    *(float2*)&dst[(er + 8) * 128 + cn] = make_float2(c[mi][nj][2], c[mi][nj][3]);
                }
            }
        }
        gbar();
        // ---- S5: finalize z_t (reduce + fused scale GEMV + reparam), fp32 ----
        if (bid < NB) {
            int b = bid, i = tid;
            float* rp   = (float*)Sm;          // [128]
            float* zrow = (float*)Sm + 128;    // [128]
            float gp = tghb[i], pp = tphb[i];
#pragma unroll
            for (int ks = 0; ks < 4; ks++) {
                gp += __ldcg(&g_gp[ks * (NB * NZ) + b * 128 + i]);
                pp += __ldcg(&g_pp[ks * (NB * NZ) + b * 128 + i]);
            }
            rp[i] = fmaxf(pp, 0.0f);
            __syncthreads();
            float s = tsb[i];
            const float* wr = tsw + (size_t)i * 128;
#pragma unroll 8
            for (int j = 0; j < 128; j += 4) {
                float4 w = *(const float4*)(wr + j);
                s += rp[j] * w.x + rp[j+1] * w.y + rp[j+2] * w.z + rp[j+3] * w.w;
            }
            float gate = sigm(gp);
            float loc = (1.0f - gate) * __ldcg(&g_loclin[b * 128 + i]) + gate * pp;
            float zv = loc + softplus_f(s) * eps[((size_t)b * NT + t) * NZ + i];
            zrow[i] = zv;
            g_zall[((size_t)t * NB + b) * NZ + i] = zv;
            __syncthreads();
            if (i < 64) g_zbf[b * 64 + i] = packbf(zrow[2*i], zrow[2*i+1]);
        }
        gbar();
    }

    // ================= phase 2 tail: obs transformer, 8 rows/group =================
    {
        float* zs = (float*)Sm;          // [8][128]
        float* hs = (float*)Sm + 1024;   // [8][512]
        const int i = tid & 63, rg = tid >> 6;
        for (int grp = bid; grp < (NT * NB) / 8; grp += G1B) {
            const size_t base = (size_t)grp * 8;     // global row = t*512 + b
            __syncthreads();                          // smem reuse guard
            for (int idx = tid; idx < 8 * 128 / 4; idx += NTH1) {
                int r = idx >> 5, cc = (idx & 31) << 2;
                *(float4*)&zs[r * 128 + cc] = __ldcg((const float4*)&g_zall[(base + r) * 128 + cc]);
            }
            __syncthreads();
            float accg[4] = {0.f, 0.f, 0.f, 0.f};
            float accp[4] = {0.f, 0.f, 0.f, 0.f};
            obs_path8(accg, ogw, ogb, oghw, zs, hs, tid);
            obs_path8(accp, opw, opb, ophw, zs, hs, tid);

            float gate[4], prop[4];
            float* ps = hs;                           // reuse hs as relu(prop) [8][64]
#pragma unroll
            for (int r4 = 0; r4 < 4; r4++) {
                gate[r4] = sigm(accg[r4] + oghb[i]);
                prop[r4] = accp[r4] + ophb[i];
                ps[(rg * 4 + r4) * 64 + i] = fmaxf(prop[r4], 0.0f);
            }
            __syncthreads();

            float s[4], loc[4];
#pragma unroll
            for (int r4 = 0; r4 < 4; r4++) { s[r4] = osb[i]; loc[r4] = olb[i]; }
            const float* wsr = osw + (size_t)i * 64;
            for (int j = 0; j < 64; j += 4) {
                float4 wv = *(const float4*)(wsr + j);
#pragma unroll
                for (int r4 = 0; r4 < 4; r4++) {
                    const float* p = &ps[(rg * 4 + r4) * 64 + j];
                    s[r4] += p[0] * wv.x + p[1] * wv.y + p[2] * wv.z + p[3] * wv.w;
                }
            }
            const float* wlr = olw + (size_t)i * 128;
            for (int k = 0; k < 128; k += 4) {
                float4 wv = *(const float4*)(wlr + k);
#pragma unroll
                for (int r4 = 0; r4 < 4; r4++) {
                    const float* zp = &zs[(rg * 4 + r4) * 128 + k];
                    loc[r4] += zp[0] * wv.x + zp[1] * wv.y + zp[2] * wv.z + zp[3] * wv.w;
                }
            }
#pragma unroll
            for (int r4 = 0; r4 < 4; r4++) {
                size_t gr = base + rg * 4 + r4;
                int tt = (int)(gr >> 9);
                int bb = (int)(gr & 511);
                float lo = (1.0f - gate[r4]) * loc[r4] + gate[r4] * prop[r4];
                float sc = softplus_f(s[r4]);
                out[((size_t)bb * NT + tt) * 128 + i]      = lo;
                out[((size_t)bb * NT + tt) * 128 + 64 + i] = sc;
            }
        }
    }
}

// ---------------- host launcher: ONE graph node ----------------
extern "C" void kernel_launch(void* const* d_in, const int* in_sizes, int n_in,
                              void* d_out, int out_size)
{
    (void)in_sizes; (void)n_in; (void)out_size;
    const float* eps      = (const float*)d_in[1];
    const float* z0       = (const float*)d_in[2];
    const float* h0       = (const float*)d_in[3];
    const float* gru_w_ih = (const float*)d_in[4];
    const float* gru_b_ih = (const float*)d_in[5];
    const float* gru_w_hh = (const float*)d_in[6];
    const float* gru_b_hh = (const float*)d_in[7];
    const float* tg_ih_w  = (const float*)d_in[8];
    const float* tg_ih_b  = (const float*)d_in[9];
    const float* tg_hz_w  = (const float*)d_in[10];
    const float* tg_hz_b  = (const float*)d_in[11];
    const float* tp_ih_w  = (const float*)d_in[12];
    const float* tp_ih_b  = (const float*)d_in[13];
    const float* tp_hz_w  = (const float*)d_in[14];
    const float* tp_hz_b  = (const float*)d_in[15];
    const float* tl_w     = (const float*)d_in[16];
    const float* tl_b     = (const float*)d_in[17];
    const float* ts_w     = (const float*)d_in[18];
    const float* ts_b     = (const float*)d_in[19];
    const float* og_ih_w  = (const float*)d_in[20];
    const float* og_ih_b  = (const float*)d_in[21];
    const float* og_hz_w  = (const float*)d_in[22];
    const float* og_hz_b  = (const float*)d_in[23];
    const float* op_ih_w  = (const float*)d_in[24];
    const float* op_ih_b  = (const float*)d_in[25];
    const float* op_hz_w  = (const float*)d_in[26];
    const float* op_hz_b  = (const float*)d_in[27];
    const float* ol_w     = (const float*)d_in[28];
    const float* ol_b     = (const float*)d_in[29];
    const float* os_w     = (const float*)d_in[30];
    const float* os_b     = (const float*)d_in[31];
    float* out = (float*)d_out;

    ssm_kernel<<<G1B, NTH1>>>(eps, z0, h0,
        gru_w_ih, gru_b_ih, gru_w_hh, gru_b_hh,
        tg_ih_w, tg_ih_b, tg_hz_w, tg_hz_b,
        tp_ih_w, tp_ih_b, tp_hz_w, tp_hz_b,
        tl_w, tl_b, ts_w, ts_b,
        og_ih_w, og_ih_b, og_hz_w, og_hz_b,
        op_ih_w, op_ih_b, op_hz_w, op_hz_b,
        ol_w, ol_b, os_w, os_b, out);
}

// round 16
// speedup vs baseline: 4.1227x; 1.0485x over previous
#include <cuda_runtime.h>
#include <cuda_bf16.h>
#include <math.h>

#define NB 512
#define NT 256
#define NZ 128
#define NX 64
#define NR 1024
#define G1B 592         // persistent grid: 4 blocks/SM on 148 SMs, all co-resident
#define NTH1 128

// ---------------- device scratch (static: no allocation allowed) ----------------
__device__ __align__(16) float    g_h[NB * NR];          // fp32 recurrence carry
__device__ __align__(16) unsigned g_hbf[NB * 512];       // bf16x2 of h   [512][512w]
__device__ __align__(16) unsigned g_zbf[NB * 64];        // bf16x2 of z   [512][64w]
__device__ __align__(16) float    g_rz[NB * 2048];
__device__ __align__(16) float    g_in[NB * NR];
__device__ __align__(16) float    g_hn[NB * NR];
__device__ __align__(16) unsigned g_hidbf[NB * 1024];    // bf16x2 relu(hid) [512][1024w]
__device__ __align__(16) float    g_loclin[NB * NZ];
__device__ __align__(16) float    g_gp[4 * NB * NZ];
__device__ __align__(16) float    g_pp[4 * NB * NZ];
__device__ __align__(16) float    g_zall[(size_t)NT * NB * NZ];  // [T,B,Z] fp32
// bf16 weight copies (converted once per launch), word = bf16x2 along K
__device__ __align__(16) unsigned g_wihb[3072 * 64];
__device__ __align__(16) unsigned g_whhb[3072 * 512];
__device__ __align__(16) unsigned g_tgwb[1024 * 512];
__device__ __align__(16) unsigned g_tpwb[1024 * 512];
__device__ __align__(16) unsigned g_tghwb[NZ * 512];
__device__ __align__(16) unsigned g_tphwb[NZ * 512];
__device__ __align__(16) unsigned g_tlwb[NZ * 512];
__device__ unsigned g_bar;   // zero-init; monotonic tickets, never reset

// ---------------- helpers ----------------
__device__ __forceinline__ float sigm(float x) { return 1.0f / (1.0f + expf(-x)); }
__device__ __forceinline__ float softplus_f(float x) {
    return fmaxf(x, 0.0f) + log1pf(expf(-fabsf(x)));
}
__device__ __forceinline__ unsigned packbf(float lo, float hi) {
    unsigned r;
    asm("cvt.rn.bf16x2.f32 %0, %1, %2;" : "=r"(r) : "f"(hi), "f"(lo));
    return r;
}
__device__ __forceinline__ void mma_bf16(float c[4],
    unsigned a0, unsigned a1, unsigned a2, unsigned a3, unsigned b0, unsigned b1)
{
    asm volatile(
        "mma.sync.aligned.m16n8k16.row.col.f32.bf16.bf16.f32 "
        "{%0,%1,%2,%3},{%4,%5,%6,%7},{%8,%9},{%0,%1,%2,%3};"
        : "+f"(c[0]), "+f"(c[1]), "+f"(c[2]), "+f"(c[3])
        : "r"(a0), "r"(a1), "r"(a2), "r"(a3), "r"(b0), "r"(b1));
}
__device__ __forceinline__ void ldmx4(unsigned& r0, unsigned& r1, unsigned& r2, unsigned& r3,
                                      unsigned saddr)
{
    asm volatile("ldmatrix.sync.aligned.m8n8.x4.shared.b16 {%0,%1,%2,%3}, [%4];"
        : "=r"(r0), "=r"(r1), "=r"(r2), "=r"(r3) : "r"(saddr));
}
// XOR swizzle: 64 rows x 32 words; conflict-free for ldmatrix rows and cp.async STS
__device__ __forceinline__ int swz(int row, int w) {
    return (row << 5) + (w ^ ((row & 7) << 2));
}
__device__ __forceinline__ void cpa16(unsigned saddr, const void* g) {
    asm volatile("cp.async.cg.shared.global [%0], [%1], 16;" :: "r"(saddr), "l"(g));
}
#define CP_COMMIT() asm volatile("cp.async.commit_group;" ::: "memory")
#define CP_WAIT0()  asm volatile("cp.async.wait_group 0;" ::: "memory")

// Software grid barrier (monotonic tickets; nanosleep backoff on the spin)
__device__ __forceinline__ void gbar() {
    __syncthreads();
    if (threadIdx.x == 0) {
        __threadfence();
        unsigned t = atomicAdd(&g_bar, 1u);
        unsigned tgt = (t / G1B + 1u) * G1B;
        while (*((volatile unsigned*)&g_bar) < tgt) { __nanosleep(64); }
    }
    __syncthreads();
}

// ---- bf16 TC tile worker: block 64x64, 4 warps of 32x32, BK=64 ----
// cp.async double-buffered, ONE sync per chunk:
//   wait(ch) -> sync -> prefetch(ch+1 into buf of ch-1) -> compute(ch)
// Fragments loaded with ldmatrix.x4 (verified identical per-lane mapping to the
// scalar LDS pattern). Smem bytes: [0,8K) A buf0, [8K,16K) A buf1,
// [16K,24K) W buf0, [24K,32K) W buf1.
__device__ __forceinline__ void mm_bf(float c[2][4][4],
    const unsigned* __restrict__ A, int ldaw,
    const unsigned* __restrict__ W, int ldww, int K,
    int bm, int bn, unsigned smb)
{
    const int tid = threadIdx.x;
    const int lane = tid & 31, wid = tid >> 5;
    const int m_off = (wid & 1) << 5, n_off = (wid >> 1) << 5;
    // staging: each thread copies half a row (16 words) per tile
    const int srow = tid >> 1, shalf = (tid & 1) << 4;
    const int d0 = swz(srow, shalf) << 2, d1 = swz(srow, shalf + 4) << 2,
              d2 = swz(srow, shalf + 8) << 2, d3 = swz(srow, shalf + 12) << 2;
    const unsigned* Arow = A + (size_t)(bm + srow) * ldaw + shalf;
    const unsigned* Wrow = W + (size_t)(bn + srow) * ldww + shalf;
    const int nch = K >> 6;
    // ldmatrix per-lane row/word indices (tile group g = lane>>3, row r = lane&7)
    const int ti = lane >> 3, rr = lane & 7;
    const int mrow = m_off + ((ti & 1) << 3) + rr;   // +16 per mi (doesn't change &7)
    const int kAadd = (ti >> 1) << 2;
    const int nrow = n_off + (ti << 3) + rr;
    const int xA = (mrow & 7) << 2, baseA = mrow << 5;
    const int xB = (nrow & 7) << 2, baseB = nrow << 5;

    // stage chunk 0 -> buffer 0
    {
        unsigned ab = smb, wb = smb + 16384;
        cpa16(ab + d0, Arow);     cpa16(ab + d1, Arow + 4);
        cpa16(ab + d2, Arow + 8); cpa16(ab + d3, Arow + 12);
        cpa16(wb + d0, Wrow);     cpa16(wb + d1, Wrow + 4);
        cpa16(wb + d2, Wrow + 8); cpa16(wb + d3, Wrow + 12);
        CP_COMMIT();
    }
    for (int ch = 0; ch < nch; ch++) {
        CP_WAIT0();            // my chunk-ch groups done
        __syncthreads();       // everyone's ch staged; everyone done reading ch-1
        if (ch + 1 < nch) {    // prefetch ch+1 into ch-1's buffer (now free)
            unsigned ab = smb + (((ch + 1) & 1) << 13);
            unsigned wb = ab + 16384;
            const unsigned* Ar = Arow + (ch + 1) * 32;
            const unsigned* Wr = Wrow + (ch + 1) * 32;
            cpa16(ab + d0, Ar);     cpa16(ab + d1, Ar + 4);
            cpa16(ab + d2, Ar + 8); cpa16(ab + d3, Ar + 12);
            cpa16(wb + d0, Wr);     cpa16(wb + d1, Wr + 4);
            cpa16(wb + d2, Wr + 8); cpa16(wb + d3, Wr + 12);
            CP_COMMIT();
        }
        const unsigned Abase = smb + ((ch & 1) << 13);
        const unsigned Wbase = Abase + 16384;
#pragma unroll
        for (int ks = 0; ks < 4; ks++) {
            const int kb = ks << 3;
            unsigned a[2][4], b0[4], b1[4];
            ldmx4(a[0][0], a[0][1], a[0][2], a[0][3],
                  Abase + ((baseA + ((kb + kAadd) ^ xA)) << 2));
            ldmx4(a[1][0], a[1][1], a[1][2], a[1][3],
                  Abase + ((baseA + 512 + ((kb + kAadd) ^ xA)) << 2));
            ldmx4(b0[0], b0[1], b0[2], b0[3],
                  Wbase + ((baseB + (kb ^ xB)) << 2));
            ldmx4(b1[0], b1[1], b1[2], b1[3],
                  Wbase + ((baseB + ((kb + 4) ^ xB)) << 2));
#pragma unroll
            for (int mi = 0; mi < 2; mi++)
#pragma unroll
                for (int nj = 0; nj < 4; nj++)
                    mma_bf16(c[mi][nj], a[mi][0], a[mi][1], a[mi][2], a[mi][3],
                             b0[nj], b1[nj]);
        }
    }
}

// phase-2 hidden-path helper (128 threads, 8 rows)
__device__ __forceinline__ void obs_path8(float acc[4],
    const float* __restrict__ wih, const float* __restrict__ bih,
    const float* __restrict__ whz, float* zs, float* hs, int tid)
{
    const int i = tid & 63, rg = tid >> 6;
    for (int half = 0; half < 2; half++) {
        int u0 = half * 512 + tid * 4;
        float a[4][8];
#pragma unroll
        for (int q = 0; q < 4; q++) {
            float bq = bih[u0 + q];
#pragma unroll
            for (int r = 0; r < 8; r++) a[q][r] = bq;
        }
        const float* w0 = wih + (size_t)u0 * 128;
        for (int k = 0; k < 128; k += 4) {
            float4 wv0 = *(const float4*)(w0 + k);
            float4 wv1 = *(const float4*)(w0 + 128 + k);
            float4 wv2 = *(const float4*)(w0 + 256 + k);
            float4 wv3 = *(const float4*)(w0 + 384 + k);
#pragma unroll
            for (int r = 0; r < 8; r++) {
                float4 zv = *(const float4*)&zs[r * 128 + k];
                a[0][r] += zv.x * wv0.x + zv.y * wv0.y + zv.z * wv0.z + zv.w * wv0.w;
                a[1][r] += zv.x * wv1.x + zv.y * wv1.y + zv.z * wv1.z + zv.w * wv1.w;
                a[2][r] += zv.x * wv2.x + zv.y * wv2.y + zv.z * wv2.z + zv.w * wv2.w;
                a[3][r] += zv.x * wv3.x + zv.y * wv3.y + zv.z * wv3.z + zv.w * wv3.w;
            }
        }
#pragma unroll
        for (int r = 0; r < 8; r++)
            *(float4*)&hs[r * 512 + tid * 4] =
                make_float4(fmaxf(a[0][r], 0.f), fmaxf(a[1][r], 0.f),
                            fmaxf(a[2][r], 0.f), fmaxf(a[3][r], 0.f));
        __syncthreads();
        const float* wr = whz + (size_t)i * 1024 + half * 512;
        for (int k = 0; k < 512; k += 4) {
            float4 wv = *(const float4*)(wr + k);
#pragma unroll
            for (int r4 = 0; r4 < 4; r4++) {
                const float* h = &hs[(rg * 4 + r4) * 512 + k];
                acc[r4] += h[0] * wv.x + h[1] * wv.y + h[2] * wv.z + h[3] * wv.w;
            }
        }
        __syncthreads();
    }
}

// ---------------- THE kernel: init + recurrence + obs, one launch ----------------
__global__ void __launch_bounds__(NTH1, 4) ssm_kernel(
    const float* __restrict__ eps,
    const float* __restrict__ z0,   const float* __restrict__ h0,
    const float* __restrict__ w_ih, const float* __restrict__ b_ih,
    const float* __restrict__ w_hh, const float* __restrict__ b_hh,
    const float* __restrict__ tgw,  const float* __restrict__ tgb,
    const float* __restrict__ tghw, const float* __restrict__ tghb,
    const float* __restrict__ tpw,  const float* __restrict__ tpb,
    const float* __restrict__ tphw, const float* __restrict__ tphb,
    const float* __restrict__ tlw,  const float* __restrict__ tlb,
    const float* __restrict__ tsw,  const float* __restrict__ tsb,
    const float* __restrict__ ogw,  const float* __restrict__ ogb,
    const float* __restrict__ oghw, const float* __restrict__ oghb,
    const float* __restrict__ opw,  const float* __restrict__ opb,
    const float* __restrict__ ophw, const float* __restrict__ ophb,
    const float* __restrict__ olw,  const float* __restrict__ olb,
    const float* __restrict__ osw,  const float* __restrict__ osb,
    float* __restrict__ out)
{
    __shared__ __align__(16) unsigned Sm[8192];   // 32 KB: GEMM bufs / phase2 zs+hs
    const int bid = blockIdx.x, tid = threadIdx.x;
    const int lane = tid & 31, wid = tid >> 5;
    const int m_off = (wid & 1) << 5, n_off = (wid >> 1) << 5;
    const int gq = lane >> 2, l4 = lane & 3;
    const int gidx = bid * NTH1 + tid, gstride = G1B * NTH1;
    const unsigned smb = (unsigned)__cvta_generic_to_shared(Sm);

    // ---- per-launch init: bf16 weight copies + state ----
    for (int i = gidx; i < 3072 * 64;  i += gstride) g_wihb[i]  = packbf(w_ih[2*i], w_ih[2*i+1]);
    for (int i = gidx; i < 3072 * 512; i += gstride) g_whhb[i]  = packbf(w_hh[2*i], w_hh[2*i+1]);
    for (int i = gidx; i < 1024 * 512; i += gstride) g_tgwb[i]  = packbf(tgw[2*i], tgw[2*i+1]);
    for (int i = gidx; i < 1024 * 512; i += gstride) g_tpwb[i]  = packbf(tpw[2*i], tpw[2*i+1]);
    for (int i = gidx; i < NZ * 512;   i += gstride) g_tghwb[i] = packbf(tghw[2*i], tghw[2*i+1]);
    for (int i = gidx; i < NZ * 512;   i += gstride) g_tphwb[i] = packbf(tphw[2*i], tphw[2*i+1]);
    for (int i = gidx; i < NZ * 512;   i += gstride) g_tlwb[i]  = packbf(tlw[2*i], tlw[2*i+1]);
    for (int i = gidx; i < NB * 512;   i += gstride) {
        float v0 = h0[(2*i) & (NR-1)], v1 = h0[(2*i+1) & (NR-1)];
        *(float2*)&g_h[2*i] = make_float2(v0, v1);
        g_hbf[i] = packbf(v0, v1);
    }
    for (int i = gidx; i < NB * 64;    i += gstride)
        g_zbf[i] = packbf(z0[(2*i) & (NZ-1)], z0[(2*i+1) & (NZ-1)]);
    gbar();

    for (int t = 0; t < NT; t++) {
        // ---- S1: GRU gate pre-activations [512,3072], K = 1024(h)+128(z) ----
        for (int tile = bid; tile < 384; tile += G1B) {
            int nt = tile / 8, mt = tile & 7;
            int bm = mt << 6, bn = nt << 6;
            float c[2][4][4] = {};
            if (nt < 32) {      // r,z columns: gi+gh summed
                mm_bf(c, g_hbf, 512, g_whhb, 512, NR, bm, bn, smb);
                mm_bf(c, g_zbf, 64,  g_wihb, 64,  NZ, bm, bn, smb);
#pragma unroll
                for (int mi = 0; mi < 2; mi++) {
                    int er = bm + m_off + (mi << 4) + gq;
#pragma unroll
                    for (int nj = 0; nj < 4; nj++) {
                        int cn = bn + n_off + (nj << 3) + (l4 << 1);
                        float b0 = b_ih[cn] + b_hh[cn], b1 = b_ih[cn+1] + b_hh[cn+1];
                        *(float2*)&g_rz[er * 2048 + cn]       = make_float2(c[mi][nj][0] + b0, c[mi][nj][1] + b1);
                        *(float2*)&g_rz[(er + 8) * 2048 + cn] = make_float2(c[mi][nj][2] + b0, c[mi][nj][3] + b1);
                    }
                }
            } else {            // n columns: i_n and h_n separately
                mm_bf(c, g_zbf, 64, g_wihb, 64, NZ, bm, bn, smb);
#pragma unroll
                for (int mi = 0; mi < 2; mi++) {
                    int er = bm + m_off + (mi << 4) + gq;
#pragma unroll
                    for (int nj = 0; nj < 4; nj++) {
                        int cn = bn + n_off + (nj << 3) + (l4 << 1);
                        int nn = cn - 2048;
                        *(float2*)&g_in[er * 1024 + nn]       = make_float2(c[mi][nj][0] + b_ih[cn], c[mi][nj][1] + b_ih[cn+1]);
                        *(float2*)&g_in[(er + 8) * 1024 + nn] = make_float2(c[mi][nj][2] + b_ih[cn], c[mi][nj][3] + b_ih[cn+1]);
                        c[mi][nj][0] = c[mi][nj][1] = c[mi][nj][2] = c[mi][nj][3] = 0.0f;
                    }
                }
                mm_bf(c, g_hbf, 512, g_whhb, 512, NR, bm, bn, smb);
#pragma unroll
                for (int mi = 0; mi < 2; mi++) {
                    int er = bm + m_off + (mi << 4) + gq;
#pragma unroll
                    for (int nj = 0; nj < 4; nj++) {
                        int cn = bn + n_off + (nj << 3) + (l4 << 1);
                        int nn = cn - 2048;
                        *(float2*)&g_hn[er * 1024 + nn]       = make_float2(c[mi][nj][0] + b_hh[cn], c[mi][nj][1] + b_hh[cn+1]);
                        *(float2*)&g_hn[(er + 8) * 1024 + nn] = make_float2(c[mi][nj][2] + b_hh[cn], c[mi][nj][3] + b_hh[cn+1]);
                    }
                }
            }
        }
        gbar();
        // ---- S2: GRU nonlinearity -> h_new (fp32 carry + bf16 pack) ----
        for (int idx = gidx; idx < NB * 512; idx += gstride) {
            int b = idx >> 9, w = idx & 511;
            int j = w << 1;
            float r0 = sigm(__ldcg(&g_rz[b * 2048 + j]));
            float r1 = sigm(__ldcg(&g_rz[b * 2048 + j + 1]));
            float zz0 = sigm(__ldcg(&g_rz[b * 2048 + 1024 + j]));
            float zz1 = sigm(__ldcg(&g_rz[b * 2048 + 1024 + j + 1]));
            float2 inv = __ldcg((const float2*)&g_in[b * 1024 + j]);
            float2 hnv = __ldcg((const float2*)&g_hn[b * 1024 + j]);
            float2 hp  = *(const float2*)&g_h[b * 1024 + j];
            float n0 = tanhf(inv.x + r0 * hnv.x);
            float n1 = tanhf(inv.y + r1 * hnv.y);
            float h0n = (1.0f - zz0) * n0 + zz0 * hp.x;
            float h1n = (1.0f - zz1) * n1 + zz1 * hp.y;
            *(float2*)&g_h[b * 1024 + j] = make_float2(h0n, h1n);
            g_hbf[idx] = packbf(h0n, h1n);
        }
        gbar();
        // ---- S3: hid = relu(h@[tgw;tpw]^T+b) [512,2048] + loclin [512,128] ----
        for (int tile = bid; tile < 272; tile += G1B) {
            float c[2][4][4] = {};
            if (tile < 256) {
                int nt = tile / 8, mt = tile & 7;
                int bm = mt << 6, bn = nt << 6;
                const unsigned* Wm; const float* bb; int nl;
                if (bn < 1024) { Wm = g_tgwb; bb = tgb; nl = bn; }
                else           { Wm = g_tpwb; bb = tpb; nl = bn - 1024; }
                mm_bf(c, g_hbf, 512, Wm, 512, NR, bm, nl, smb);
#pragma unroll
                for (int mi = 0; mi < 2; mi++) {
                    int er = bm + m_off + (mi << 4) + gq;
#pragma unroll
                    for (int nj = 0; nj < 4; nj++) {
                        int lc = n_off + (nj << 3) + (l4 << 1);
                        float b0 = bb[nl + lc], b1 = bb[nl + lc + 1];
                        int wcol = ((bn + n_off + (nj << 3)) >> 1) + l4;
                        g_hidbf[er * 1024 + wcol] =
                            packbf(fmaxf(c[mi][nj][0] + b0, 0.0f), fmaxf(c[mi][nj][1] + b1, 0.0f));
                        g_hidbf[(er + 8) * 1024 + wcol] =
                            packbf(fmaxf(c[mi][nj][2] + b0, 0.0f), fmaxf(c[mi][nj][3] + b1, 0.0f));
                    }
                }
            } else {
                int t2 = tile - 256;              // 0..15: loclin 8m x 2n
                int bm = (t2 >> 1) << 6, bn = (t2 & 1) << 6;
                mm_bf(c, g_hbf, 512, g_tlwb, 512, NR, bm, bn, smb);
#pragma unroll
                for (int mi = 0; mi < 2; mi++) {
                    int er = bm + m_off + (mi << 4) + gq;
#pragma unroll
                    for (int nj = 0; nj < 4; nj++) {
                        int cn = bn + n_off + (nj << 3) + (l4 << 1);
                        *(float2*)&g_loclin[er * 128 + cn]       = make_float2(c[mi][nj][0] + tlb[cn], c[mi][nj][1] + tlb[cn+1]);
                        *(float2*)&g_loclin[(er + 8) * 128 + cn] = make_float2(c[mi][nj][2] + tlb[cn], c[mi][nj][3] + tlb[cn+1]);
                    }
                }
            }
        }
        gbar();
        // ---- S4: gatep/prop [512,128] K=1024 k-split4 (128 tiles) ----
        for (int tile = bid; tile < 128; tile += G1B) {
            int gg = tile >> 6;
            int rem = tile & 63;
            int ks = rem & 3, nt = (rem >> 2) & 1, mt = rem >> 3;
            int bm = mt << 6, bn = nt << 6;
            const unsigned* Aq = g_hidbf + (gg ? 512 : 0) + (ks << 7);
            const unsigned* Wq = (gg ? g_tphwb : g_tghwb) + (ks << 7);
            float c[2][4][4] = {};
            mm_bf(c, Aq, 1024, Wq, 512, 256, bm, bn, smb);
            float* dst = (gg ? g_pp : g_gp) + ks * (NB * NZ);
#pragma unroll
            for (int mi = 0; mi < 2; mi++) {
                int er = bm + m_off + (mi << 4) + gq;
#pragma unroll
                for (int nj = 0; nj < 4; nj++) {
                    int cn = bn + n_off + (nj << 3) + (l4 << 1);
                    *(float2*)&dst[er * 128 + cn]       = make_float2(c[mi][nj][0], c[mi][nj][1]);
                    *(float2*)&dst[(er + 8) * 128 + cn] = make_float2(c[mi][nj][2], c[mi][nj][3]);
                }
            }
        }
        gbar();
        // ---- S5: finalize z_t (reduce + fused scale GEMV + reparam), fp32 ----
        if (bid < NB) {
            int b = bid, i = tid;
            float* rp   = (float*)Sm;          // [128]
            float* zrow = (float*)Sm + 128;    // [128]
            float gp = tghb[i], pp = tphb[i];
#pragma unroll
            for (int ks = 0; ks < 4; ks++) {
                gp += __ldcg(&g_gp[ks * (NB * NZ) + b * 128 + i]);
                pp += __ldcg(&g_pp[ks * (NB * NZ) + b * 128 + i]);
            }
            rp[i] = fmaxf(pp, 0.0f);
            __syncthreads();
            float s = tsb[i];
            const float* wr = tsw + (size_t)i * 128;
#pragma unroll 8
            for (int j = 0; j < 128; j += 4) {
                float4 w = *(const float4*)(wr + j);
                s += rp[j] * w.x + rp[j+1] * w.y + rp[j+2] * w.z + rp[j+3] * w.w;
            }
            float gate = sigm(gp);
            float loc = (1.0f - gate) * __ldcg(&g_loclin[b * 128 + i]) + gate * pp;
            float zv = loc + softplus_f(s) * eps[((size_t)b * NT + t) * NZ + i];
            zrow[i] = zv;
            g_zall[((size_t)t * NB + b) * NZ + i] = zv;
            __syncthreads();
            if (i < 64) g_zbf[b * 64 + i] = packbf(zrow[2*i], zrow[2*i+1]);
        }
        gbar();
    }

    // ================= phase 2 tail: obs transformer, 8 rows/group =================
    {
        float* zs = (float*)Sm;          // [8][128]
        float* hs = (float*)Sm + 1024;   // [8][512]
        const int i = tid & 63, rg = tid >> 6;
        for (int grp = bid; grp < (NT * NB) / 8; grp += G1B) {
            const size_t base = (size_t)grp * 8;     // global row = t*512 + b
            __syncthreads();                          // smem reuse guard
            for (int idx = tid; idx < 8 * 128 / 4; idx += NTH1) {
                int r = idx >> 5, cc = (idx & 31) << 2;
                *(float4*)&zs[r * 128 + cc] = __ldcg((const float4*)&g_zall[(base + r) * 128 + cc]);
            }
            __syncthreads();
            float accg[4] = {0.f, 0.f, 0.f, 0.f};
            float accp[4] = {0.f, 0.f, 0.f, 0.f};
            obs_path8(accg, ogw, ogb, oghw, zs, hs, tid);
            obs_path8(accp, opw, opb, ophw, zs, hs, tid);

            float gate[4], prop[4];
            float* ps = hs;                           // reuse hs as relu(prop) [8][64]
#pragma unroll
            for (int r4 = 0; r4 < 4; r4++) {
                gate[r4] = sigm(accg[r4] + oghb[i]);
                prop[r4] = accp[r4] + ophb[i];
                ps[(rg * 4 + r4) * 64 + i] = fmaxf(prop[r4], 0.0f);
            }
            __syncthreads();

            float s[4], loc[4];
#pragma unroll
            for (int r4 = 0; r4 < 4; r4++) { s[r4] = osb[i]; loc[r4] = olb[i]; }
            const float* wsr = osw + (size_t)i * 64;
            for (int j = 0; j < 64; j += 4) {
                float4 wv = *(const float4*)(wsr + j);
#pragma unroll
                for (int r4 = 0; r4 < 4; r4++) {
                    const float* p = &ps[(rg * 4 + r4) * 64 + j];
                    s[r4] += p[0] * wv.x + p[1] * wv.y + p[2] * wv.z + p[3] * wv.w;
                }
            }
            const float* wlr = olw + (size_t)i * 128;
            for (int k = 0; k < 128; k += 4) {
                float4 wv = *(const float4*)(wlr + k);
#pragma unroll
                for (int r4 = 0; r4 < 4; r4++) {
                    const float* zp = &zs[(rg * 4 + r4) * 128 + k];
                    loc[r4] += zp[0] * wv.x + zp[1] * wv.y + zp[2] * wv.z + zp[3] * wv.w;
                }
            }
#pragma unroll
            for (int r4 = 0; r4 < 4; r4++) {
                size_t gr = base + rg * 4 + r4;
                int tt = (int)(gr >> 9);
                int bb = (int)(gr & 511);
                float lo = (1.0f - gate[r4]) * loc[r4] + gate[r4] * prop[r4];
                float sc = softplus_f(s[r4]);
                out[((size_t)bb * NT + tt) * 128 + i]      = lo;
                out[((size_t)bb * NT + tt) * 128 + 64 + i] = sc;
            }
        }
    }
}

// ---------------- host launcher: ONE graph node ----------------
extern "C" void kernel_launch(void* const* d_in, const int* in_sizes, int n_in,
                              void* d_out, int out_size)
{
    (void)in_sizes; (void)n_in; (void)out_size;
    const float* eps      = (const float*)d_in[1];
    const float* z0       = (const float*)d_in[2];
    const float* h0       = (const float*)d_in[3];
    const float* gru_w_ih = (const float*)d_in[4];
    const float* gru_b_ih = (const float*)d_in[5];
    const float* gru_w_hh = (const float*)d_in[6];
    const float* gru_b_hh = (const float*)d_in[7];
    const float* tg_ih_w  = (const float*)d_in[8];
    const float* tg_ih_b  = (const float*)d_in[9];
    const float* tg_hz_w  = (const float*)d_in[10];
    const float* tg_hz_b  = (const float*)d_in[11];
    const float* tp_ih_w  = (const float*)d_in[12];
    const float* tp_ih_b  = (const float*)d_in[13];
    const float* tp_hz_w  = (const float*)d_in[14];
    const float* tp_hz_b  = (const float*)d_in[15];
    const float* tl_w     = (const float*)d_in[16];
    const float* tl_b     = (const float*)d_in[17];
    const float* ts_w     = (const float*)d_in[18];
    const float* ts_b     = (const float*)d_in[19];
    const float* og_ih_w  = (const float*)d_in[20];
    const float* og_ih_b  = (const float*)d_in[21];
    const float* og_hz_w  = (const float*)d_in[22];
    const float* og_hz_b  = (const float*)d_in[23];
    const float* op_ih_w  = (const float*)d_in[24];
    const float* op_ih_b  = (const float*)d_in[25];
    const float* op_hz_w  = (const float*)d_in[26];
    const float* op_hz_b  = (const float*)d_in[27];
    const float* ol_w     = (const float*)d_in[28];
    const float* ol_b     = (const float*)d_in[29];
    const float* os_w     = (const float*)d_in[30];
    const float* os_b     = (const float*)d_in[31];
    float* out = (float*)d_out;

    ssm_kernel<<<G1B, NTH1>>>(eps, z0, h0,
        gru_w_ih, gru_b_ih, gru_w_hh, gru_b_hh,
        tg_ih_w, tg_ih_b, tg_hz_w, tg_hz_b,
        tp_ih_w, tp_ih_b, tp_hz_w, tp_hz_b,
        tl_w, tl_b, ts_w, ts_b,
        og_ih_w, og_ih_b, og_hz_w, og_hz_b,
        op_ih_w, op_ih_b, op_hz_w, op_hz_b,
        ol_w, ol_b, os_w, os_b, out);
}